// round 1
// baseline (speedup 1.0000x reference)
#include <cuda_runtime.h>

#define NN   100000
#define EE   1600000
#define DINF 67
#define DPAD 68          // padded feature width (17 * float4)
#define DH   128
#define KTOT 272         // 4 * DPAD
#define NCH  17          // float4 chunks per row

// ---------------- scratch (static device memory; no allocs allowed) ----------
__device__ float g_hbuf[4][NN * DPAD];      // hop buffers h0..h3 (padded)
__device__ float g_deg[NN];
__device__ float g_dis[NN];
__device__ float g_ew[EE];
__device__ float g_Wcat[KTOT * DH];         // padded/transposed W1
__device__ float g_A1[DINF], g_B1[DINF];    // BN1 folded affine
__device__ float g_A2[DH],   g_B2[DH];      // BN2 + bias1 folded affine
__device__ float g_hmid[NN * DH];           // post layer1+BN2+lrelu
__device__ float g_y[4][NN];                // layer2 projections
__device__ float g_ta[NN], g_tb[NN];        // scalar propagation buffers

// ---------------- helpers ----------------------------------------------------
__device__ __forceinline__ void red4(float* p, float a, float b, float c, float d) {
    asm volatile("red.global.add.v4.f32 [%0], {%1, %2, %3, %4};"
                 :: "l"(p), "f"(a), "f"(b), "f"(c), "f"(d) : "memory");
}

// ---------------- kernels ----------------------------------------------------
__global__ void k_zero() {
    int i = blockIdx.x * blockDim.x + threadIdx.x;
    if (i < NN) g_deg[i] = 0.f;
    float* p = &g_hbuf[1][0];                 // slices 1..3 contiguous
    if (i < 3 * NN * DPAD) p[i] = 0.f;
}

__global__ void k_deg(const int* __restrict__ col) {
    int e = blockIdx.x * blockDim.x + threadIdx.x;
    if (e < EE) atomicAdd(&g_deg[col[e]], 1.0f);
}

__global__ void k_dis() {
    int i = blockIdx.x * blockDim.x + threadIdx.x;
    if (i < NN) {
        float d = g_deg[i];
        g_dis[i] = (d > 0.f) ? rsqrtf(d) : 0.f;
    }
}

__global__ void k_ew(const int* __restrict__ row, const int* __restrict__ col) {
    int e = blockIdx.x * blockDim.x + threadIdx.x;
    if (e < EE) g_ew[e] = g_dis[row[e]] * g_dis[col[e]];
}

__global__ void k_setup(const float* __restrict__ g1, const float* __restrict__ b1,
                        const float* __restrict__ m1, const float* __restrict__ v1,
                        const float* __restrict__ W1, const float* __restrict__ bias1,
                        const float* __restrict__ g2, const float* __restrict__ b2,
                        const float* __restrict__ m2, const float* __restrict__ v2) {
    int i = blockIdx.x * blockDim.x + threadIdx.x;
    if (i < DINF) {
        float s = g1[i] * rsqrtf(v1[i] + 1e-5f);
        g_A1[i] = s;
        g_B1[i] = b1[i] - m1[i] * s;
    }
    if (i < DH) {
        float s = g2[i] * rsqrtf(v2[i] + 1e-5f);
        g_A2[i] = s;
        g_B2[i] = (bias1[i] - m2[i]) * s + b2[i];
    }
    if (i < KTOT * DH) {
        int j = i / DH, o = i - j * DH;
        int hop = j / DPAD, d = j - hop * DPAD;
        g_Wcat[i] = (d < DINF) ? W1[(hop * DH + o) * DINF + d] : 0.f;
    }
}

__global__ void k_bn1(const float* __restrict__ x) {
    int i = blockIdx.x * blockDim.x + threadIdx.x;
    if (i >= NN * DPAD) return;
    int n = i / DPAD, d = i - n * DPAD;
    g_hbuf[0][i] = (d < DINF) ? x[n * DINF + d] * g_A1[d] + g_B1[d] : 0.f;
}

// one hop of normalized propagation: dst[col] += ew * src[row], vectorized x4
__global__ void k_prop(const float* __restrict__ src, float* __restrict__ dst,
                       const int* __restrict__ row, const int* __restrict__ col) {
    int idx = blockIdx.x * blockDim.x + threadIdx.x;
    if (idx >= EE * NCH) return;
    int e = idx / NCH, c = idx - e * NCH;
    int r = row[e], t = col[e];
    float w = g_ew[e];
    const float4 v = *reinterpret_cast<const float4*>(src + r * DPAD + c * 4);
    red4(dst + t * DPAD + c * 4, v.x * w, v.y * w, v.z * w, v.w * w);
}

// C[N,128] = [h0|h1|h2|h3] (N x 272) @ Wcat (272 x 128), fused BN2+bias1+leaky
__global__ void __launch_bounds__(256) k_gemm() {
    __shared__ float As[8][128];
    __shared__ float Bs[8][128];
    const int bm  = blockIdx.x * 128;
    const int tid = threadIdx.x;
    const int tx  = tid & 15;       // output col group
    const int ty  = tid >> 4;       // output row group
    float acc[8][8];
#pragma unroll
    for (int i = 0; i < 8; i++)
#pragma unroll
        for (int j = 0; j < 8; j++) acc[i][j] = 0.f;

    for (int k0 = 0; k0 < KTOT; k0 += 8) {
#pragma unroll
        for (int l = 0; l < 4; l++) {
            int li = tid + l * 256;          // 0..1023
            int m = li >> 3, kk = li & 7;
            int n = bm + m;
            int j = k0 + kk;
            int hop = j / DPAD, d = j - hop * DPAD;
            As[kk][m] = (n < NN) ? g_hbuf[hop][n * DPAD + d] : 0.f;
        }
#pragma unroll
        for (int l = 0; l < 4; l++) {
            int li = tid + l * 256;
            int kk = li >> 7, o = li & 127;
            Bs[kk][o] = g_Wcat[(k0 + kk) * DH + o];
        }
        __syncthreads();
#pragma unroll
        for (int kk = 0; kk < 8; kk++) {
            float a[8], b[8];
#pragma unroll
            for (int i = 0; i < 8; i++) a[i] = As[kk][ty * 8 + i];
#pragma unroll
            for (int i = 0; i < 8; i++) b[i] = Bs[kk][tx * 8 + i];
#pragma unroll
            for (int i = 0; i < 8; i++)
#pragma unroll
                for (int j = 0; j < 8; j++) acc[i][j] += a[i] * b[j];
        }
        __syncthreads();
    }
#pragma unroll
    for (int i = 0; i < 8; i++) {
        int n = bm + ty * 8 + i;
        if (n >= NN) continue;
#pragma unroll
        for (int j = 0; j < 8; j++) {
            int o = tx * 8 + j;
            float v = acc[i][j] * g_A2[o] + g_B2[o];
            v = (v > 0.f) ? v : 0.01f * v;      // leaky relu
            g_hmid[n * DH + o] = v;
        }
    }
}

// y[k][n] = dot(hmid[n,:], W2[k][0][:]) ; one warp per node
__global__ void k_y(const float* __restrict__ W2) {
    int gt = blockIdx.x * blockDim.x + threadIdx.x;
    int lane = gt & 31, warp = gt >> 5;
    int nwarps = (gridDim.x * blockDim.x) >> 5;
    float4 w0 = *reinterpret_cast<const float4*>(W2 + 0 * DH + lane * 4);
    float4 w1 = *reinterpret_cast<const float4*>(W2 + 1 * DH + lane * 4);
    float4 w2 = *reinterpret_cast<const float4*>(W2 + 2 * DH + lane * 4);
    float4 w3 = *reinterpret_cast<const float4*>(W2 + 3 * DH + lane * 4);
    for (int n = warp; n < NN; n += nwarps) {
        float4 h = *reinterpret_cast<const float4*>(g_hmid + n * DH + lane * 4);
        float s0 = h.x * w0.x + h.y * w0.y + h.z * w0.z + h.w * w0.w;
        float s1 = h.x * w1.x + h.y * w1.y + h.z * w1.z + h.w * w1.w;
        float s2 = h.x * w2.x + h.y * w2.y + h.z * w2.z + h.w * w2.w;
        float s3 = h.x * w3.x + h.y * w3.y + h.z * w3.z + h.w * w3.w;
#pragma unroll
        for (int off = 16; off > 0; off >>= 1) {
            s0 += __shfl_xor_sync(0xFFFFFFFFu, s0, off);
            s1 += __shfl_xor_sync(0xFFFFFFFFu, s1, off);
            s2 += __shfl_xor_sync(0xFFFFFFFFu, s2, off);
            s3 += __shfl_xor_sync(0xFFFFFFFFu, s3, off);
        }
        if (lane == 0) {
            g_y[0][n] = s0; g_y[1][n] = s1; g_y[2][n] = s2; g_y[3][n] = s3;
        }
    }
}

__global__ void k_copy(float* __restrict__ dst, const float* __restrict__ src) {
    int i = blockIdx.x * blockDim.x + threadIdx.x;
    if (i < NN) dst[i] = src[i];
}

__global__ void k_init_out(float* __restrict__ out, const float* __restrict__ bias2) {
    int i = blockIdx.x * blockDim.x + threadIdx.x;
    if (i < NN) out[i] = g_y[0][i] + bias2[0];
}

// scalar hop: dst[col] += ew * src[row]
__global__ void k_sprop(const float* __restrict__ src, float* __restrict__ dst,
                        const int* __restrict__ row, const int* __restrict__ col) {
    int e = blockIdx.x * blockDim.x + threadIdx.x;
    if (e < EE) atomicAdd(&dst[col[e]], g_ew[e] * src[row[e]]);
}

// ---------------- launch -----------------------------------------------------
extern "C" void kernel_launch(void* const* d_in, const int* in_sizes, int n_in,
                              void* d_out, int out_size) {
    const float* x     = (const float*)d_in[0];
    const int*   ei    = (const int*)  d_in[1];
    const float* g1    = (const float*)d_in[2];
    const float* b1    = (const float*)d_in[3];
    const float* m1    = (const float*)d_in[4];
    const float* v1    = (const float*)d_in[5];
    const float* W1    = (const float*)d_in[6];
    const float* bias1 = (const float*)d_in[7];
    const float* g2    = (const float*)d_in[8];
    const float* b2    = (const float*)d_in[9];
    const float* m2    = (const float*)d_in[10];
    const float* v2    = (const float*)d_in[11];
    const float* W2    = (const float*)d_in[12];
    const float* bias2 = (const float*)d_in[13];
    float* out = (float*)d_out;

    const int* row = ei;
    const int* col = ei + EE;

    const int T = 256;
    // scratch pointers (device symbols usable directly inside kernels)
    // zero deg + hop slices 1..3
    k_zero<<<(3 * NN * DPAD + T - 1) / T, T>>>();
    k_deg<<<(EE + T - 1) / T, T>>>(col);
    k_dis<<<(NN + T - 1) / T, T>>>();
    k_ew<<<(EE + T - 1) / T, T>>>(row, col);
    k_setup<<<(KTOT * DH + T - 1) / T, T>>>(g1, b1, m1, v1, W1, bias1, g2, b2, m2, v2);
    k_bn1<<<(NN * DPAD + T - 1) / T, T>>>(x);

    // layer-1 propagation: 3 hops at width 68
    {
        float* h0; float* h1; float* h2; float* h3;
        cudaGetSymbolAddress((void**)&h0, g_hbuf);
        h1 = h0 + NN * DPAD; h2 = h1 + NN * DPAD; h3 = h2 + NN * DPAD;
        int blocks = (EE * NCH + T - 1) / T;
        k_prop<<<blocks, T>>>(h0, h1, row, col);
        k_prop<<<blocks, T>>>(h1, h2, row, col);
        k_prop<<<blocks, T>>>(h2, h3, row, col);
    }

    // fused GEMM + bias1 + BN2 + leaky
    k_gemm<<<(NN + 127) / 128, 256>>>();

    // layer-2 projections to 4 scalar channels
    k_y<<<(NN * 32 + T - 1) / T, T>>>(W2);

    // Horner on scalar channels: out = y0 + A(y1 + A(y2 + A y3)) + bias2
    {
        float* ta; float* tb; float* y0;
        cudaGetSymbolAddress((void**)&ta, g_ta);
        cudaGetSymbolAddress((void**)&tb, g_tb);
        cudaGetSymbolAddress((void**)&y0, g_y);
        float* y1 = y0 + NN; float* y2 = y1 + NN; float* y3 = y2 + NN;
        int bn = (NN + T - 1) / T, be = (EE + T - 1) / T;
        k_copy<<<bn, T>>>(tb, y2);
        k_sprop<<<be, T>>>(y3, tb, row, col);
        k_copy<<<bn, T>>>(ta, y1);
        k_sprop<<<be, T>>>(tb, ta, row, col);
        k_init_out<<<bn, T>>>(out, bias2);
        k_sprop<<<be, T>>>(ta, out, row, col);
    }
    (void)in_sizes; (void)n_in; (void)out_size;
}

// round 2
// speedup vs baseline: 1.4852x; 1.4852x over previous
#include <cuda_runtime.h>

#define NN   100000
#define EE   1600000
#define DINF 67
#define DPAD 68          // padded feature width (17 * float4)
#define DH   128
#define KTOT 272         // 4 * DPAD
#define NCH  17          // float4 chunks per row
#define SCAN_B 1024
#define NBLK   98        // ceil(100000/1024)

// ---------------- scratch (static device memory; no allocs allowed) ----------
__device__ float g_hbuf[4][NN * DPAD];      // hop buffers h0..h3 (padded)
__device__ int   g_degi[NN];
__device__ float g_dis[NN];
__device__ int   g_off[NN + 1];             // CSC offsets
__device__ int   g_cursor[NN];
__device__ int   g_blocksum[NBLK + 1];
__device__ int   g_csc_src[EE];             // source node per CSC slot
__device__ float g_csc_w[EE];               // normalized weight per CSC slot
__device__ float g_Wcat[KTOT * DH];         // padded/transposed W1
__device__ float g_A1[DINF], g_B1[DINF];    // BN1 folded affine
__device__ float g_A2[DH],   g_B2[DH];      // BN2 + bias1 folded affine
__device__ float g_hmid[NN * DH];           // post layer1+BN2+lrelu
__device__ float g_y[4][NN];                // layer2 projections
__device__ float g_ta[NN], g_tb[NN];        // scalar propagation buffers

// ---------------- kernels ----------------------------------------------------
__global__ void k_zero() {
    int i = blockIdx.x * blockDim.x + threadIdx.x;
    if (i < NN) g_degi[i] = 0;
}

__global__ void k_deg(const int* __restrict__ col) {
    int e = blockIdx.x * blockDim.x + threadIdx.x;
    if (e < EE) atomicAdd(&g_degi[col[e]], 1);
}

// block-level inclusive scan -> exclusive offsets (partial) + block totals
__global__ void k_scanA() {
    __shared__ int s[SCAN_B];
    int g = blockIdx.x * SCAN_B + threadIdx.x;
    int v = (g < NN) ? g_degi[g] : 0;
    s[threadIdx.x] = v;
    __syncthreads();
#pragma unroll
    for (int d = 1; d < SCAN_B; d <<= 1) {
        int t = (threadIdx.x >= d) ? s[threadIdx.x - d] : 0;
        __syncthreads();
        s[threadIdx.x] += t;
        __syncthreads();
    }
    if (g < NN) g_off[g] = s[threadIdx.x] - v;   // exclusive within block
    if (threadIdx.x == SCAN_B - 1) g_blocksum[blockIdx.x] = s[SCAN_B - 1];
}

__global__ void k_scanB() {
    if (threadIdx.x == 0) {
        int running = 0;
        for (int b = 0; b < NBLK; b++) {
            int t = g_blocksum[b];
            g_blocksum[b] = running;
            running += t;
        }
        g_off[NN] = running;    // == EE
    }
}

__global__ void k_scanC() {
    int g = blockIdx.x * SCAN_B + threadIdx.x;
    if (g < NN) {
        int o = g_off[g] + g_blocksum[blockIdx.x];
        g_off[g] = o;
        g_cursor[g] = o;
        int d = g_degi[g];
        g_dis[g] = (d > 0) ? rsqrtf((float)d) : 0.f;
    }
}

__global__ void k_fill(const int* __restrict__ row, const int* __restrict__ col) {
    int e = blockIdx.x * blockDim.x + threadIdx.x;
    if (e < EE) {
        int c = col[e], r = row[e];
        int p = atomicAdd(&g_cursor[c], 1);
        g_csc_src[p] = r;
        g_csc_w[p] = g_dis[r] * g_dis[c];
    }
}

__global__ void k_setup(const float* __restrict__ g1, const float* __restrict__ b1,
                        const float* __restrict__ m1, const float* __restrict__ v1,
                        const float* __restrict__ W1, const float* __restrict__ bias1,
                        const float* __restrict__ g2, const float* __restrict__ b2,
                        const float* __restrict__ m2, const float* __restrict__ v2) {
    int i = blockIdx.x * blockDim.x + threadIdx.x;
    if (i < DINF) {
        float s = g1[i] * rsqrtf(v1[i] + 1e-5f);
        g_A1[i] = s;
        g_B1[i] = b1[i] - m1[i] * s;
    }
    if (i < DH) {
        float s = g2[i] * rsqrtf(v2[i] + 1e-5f);
        g_A2[i] = s;
        g_B2[i] = (bias1[i] - m2[i]) * s + b2[i];
    }
    if (i < KTOT * DH) {
        int j = i / DH, o = i - j * DH;
        int hop = j / DPAD, d = j - hop * DPAD;
        g_Wcat[i] = (d < DINF) ? W1[(hop * DH + o) * DINF + d] : 0.f;
    }
}

__global__ void k_bn1(const float* __restrict__ x) {
    int i = blockIdx.x * blockDim.x + threadIdx.x;
    if (i >= NN * DPAD) return;
    int n = i / DPAD, d = i - n * DPAD;
    g_hbuf[0][i] = (d < DINF) ? x[n * DINF + d] * g_A1[d] + g_B1[d] : 0.f;
}

// gather hop: dst[n] = sum_{in-edges} w * src[r], vectorized x4, no atomics
__global__ void k_hop(const float* __restrict__ src, float* __restrict__ dst) {
    int idx = blockIdx.x * blockDim.x + threadIdx.x;
    if (idx >= NN * NCH) return;
    int n = idx / NCH, c = idx - n * NCH;
    int s = g_off[n], e2 = g_off[n + 1];
    float ax = 0.f, ay = 0.f, az = 0.f, aw = 0.f;
    for (int i = s; i < e2; i++) {
        int r = g_csc_src[i];
        float w = g_csc_w[i];
        const float4 v = *reinterpret_cast<const float4*>(src + r * DPAD + c * 4);
        ax += w * v.x; ay += w * v.y; az += w * v.z; aw += w * v.w;
    }
    float4 o; o.x = ax; o.y = ay; o.z = az; o.w = aw;
    *reinterpret_cast<float4*>(dst + n * DPAD + c * 4) = o;
}

// C[N,128] = [h0|h1|h2|h3] (N x 272) @ Wcat (272 x 128), fused BN2+bias1+leaky
__global__ void __launch_bounds__(256) k_gemm() {
    __shared__ float As[8][128];
    __shared__ float Bs[8][128];
    const int bm  = blockIdx.x * 128;
    const int tid = threadIdx.x;
    const int tx  = tid & 15;       // output col group
    const int ty  = tid >> 4;       // output row group
    float acc[8][8];
#pragma unroll
    for (int i = 0; i < 8; i++)
#pragma unroll
        for (int j = 0; j < 8; j++) acc[i][j] = 0.f;

    for (int k0 = 0; k0 < KTOT; k0 += 8) {
#pragma unroll
        for (int l = 0; l < 4; l++) {
            int li = tid + l * 256;          // 0..1023
            int m = li >> 3, kk = li & 7;
            int n = bm + m;
            int j = k0 + kk;
            int hop = j / DPAD, d = j - hop * DPAD;
            As[kk][m] = (n < NN) ? g_hbuf[hop][n * DPAD + d] : 0.f;
        }
#pragma unroll
        for (int l = 0; l < 4; l++) {
            int li = tid + l * 256;
            int kk = li >> 7, o = li & 127;
            Bs[kk][o] = g_Wcat[(k0 + kk) * DH + o];
        }
        __syncthreads();
#pragma unroll
        for (int kk = 0; kk < 8; kk++) {
            float a[8], b[8];
#pragma unroll
            for (int i = 0; i < 8; i++) a[i] = As[kk][ty * 8 + i];
#pragma unroll
            for (int i = 0; i < 8; i++) b[i] = Bs[kk][tx * 8 + i];
#pragma unroll
            for (int i = 0; i < 8; i++)
#pragma unroll
                for (int j = 0; j < 8; j++) acc[i][j] += a[i] * b[j];
        }
        __syncthreads();
    }
#pragma unroll
    for (int i = 0; i < 8; i++) {
        int n = bm + ty * 8 + i;
        if (n >= NN) continue;
#pragma unroll
        for (int j = 0; j < 8; j++) {
            int o = tx * 8 + j;
            float v = acc[i][j] * g_A2[o] + g_B2[o];
            v = (v > 0.f) ? v : 0.01f * v;      // leaky relu
            g_hmid[n * DH + o] = v;
        }
    }
}

// y[k][n] = dot(hmid[n,:], W2[k][0][:]) ; one warp per node
__global__ void k_y(const float* __restrict__ W2) {
    int gt = blockIdx.x * blockDim.x + threadIdx.x;
    int lane = gt & 31, warp = gt >> 5;
    int nwarps = (gridDim.x * blockDim.x) >> 5;
    float4 w0 = *reinterpret_cast<const float4*>(W2 + 0 * DH + lane * 4);
    float4 w1 = *reinterpret_cast<const float4*>(W2 + 1 * DH + lane * 4);
    float4 w2 = *reinterpret_cast<const float4*>(W2 + 2 * DH + lane * 4);
    float4 w3 = *reinterpret_cast<const float4*>(W2 + 3 * DH + lane * 4);
    for (int n = warp; n < NN; n += nwarps) {
        float4 h = *reinterpret_cast<const float4*>(g_hmid + n * DH + lane * 4);
        float s0 = h.x * w0.x + h.y * w0.y + h.z * w0.z + h.w * w0.w;
        float s1 = h.x * w1.x + h.y * w1.y + h.z * w1.z + h.w * w1.w;
        float s2 = h.x * w2.x + h.y * w2.y + h.z * w2.z + h.w * w2.w;
        float s3 = h.x * w3.x + h.y * w3.y + h.z * w3.z + h.w * w3.w;
#pragma unroll
        for (int off = 16; off > 0; off >>= 1) {
            s0 += __shfl_xor_sync(0xFFFFFFFFu, s0, off);
            s1 += __shfl_xor_sync(0xFFFFFFFFu, s1, off);
            s2 += __shfl_xor_sync(0xFFFFFFFFu, s2, off);
            s3 += __shfl_xor_sync(0xFFFFFFFFu, s3, off);
        }
        if (lane == 0) {
            g_y[0][n] = s0; g_y[1][n] = s1; g_y[2][n] = s2; g_y[3][n] = s3;
        }
    }
}

// scalar gather hop: dst[n] = addin[n] (+bias) + sum w*src[r]
__global__ void k_shop(float* __restrict__ dst, const float* __restrict__ addin,
                       const float* __restrict__ src, const float* __restrict__ bias) {
    int n = blockIdx.x * blockDim.x + threadIdx.x;
    if (n >= NN) return;
    float acc = addin[n] + (bias ? bias[0] : 0.f);
    int e2 = g_off[n + 1];
    for (int i = g_off[n]; i < e2; i++)
        acc += g_csc_w[i] * src[g_csc_src[i]];
    dst[n] = acc;
}

// ---------------- launch -----------------------------------------------------
extern "C" void kernel_launch(void* const* d_in, const int* in_sizes, int n_in,
                              void* d_out, int out_size) {
    const float* x     = (const float*)d_in[0];
    const int*   ei    = (const int*)  d_in[1];
    const float* g1    = (const float*)d_in[2];
    const float* b1    = (const float*)d_in[3];
    const float* m1    = (const float*)d_in[4];
    const float* v1    = (const float*)d_in[5];
    const float* W1    = (const float*)d_in[6];
    const float* bias1 = (const float*)d_in[7];
    const float* g2    = (const float*)d_in[8];
    const float* b2    = (const float*)d_in[9];
    const float* m2    = (const float*)d_in[10];
    const float* v2    = (const float*)d_in[11];
    const float* W2    = (const float*)d_in[12];
    const float* bias2 = (const float*)d_in[13];
    float* out = (float*)d_out;

    const int* row = ei;
    const int* col = ei + EE;

    const int T = 256;

    // CSC build
    k_zero<<<(NN + T - 1) / T, T>>>();
    k_deg<<<(EE + T - 1) / T, T>>>(col);
    k_scanA<<<NBLK, SCAN_B>>>();
    k_scanB<<<1, 32>>>();
    k_scanC<<<NBLK, SCAN_B>>>();
    k_fill<<<(EE + T - 1) / T, T>>>(row, col);

    k_setup<<<(KTOT * DH + T - 1) / T, T>>>(g1, b1, m1, v1, W1, bias1, g2, b2, m2, v2);
    k_bn1<<<(NN * DPAD + T - 1) / T, T>>>(x);

    // layer-1 propagation: 3 gather hops at width 68
    {
        float* h0; float* h1; float* h2; float* h3;
        cudaGetSymbolAddress((void**)&h0, g_hbuf);
        h1 = h0 + NN * DPAD; h2 = h1 + NN * DPAD; h3 = h2 + NN * DPAD;
        int blocks = (NN * NCH + T - 1) / T;
        k_hop<<<blocks, T>>>(h0, h1);
        k_hop<<<blocks, T>>>(h1, h2);
        k_hop<<<blocks, T>>>(h2, h3);
    }

    // fused GEMM + bias1 + BN2 + leaky
    k_gemm<<<(NN + 127) / 128, 256>>>();

    // layer-2 projections to 4 scalar channels
    k_y<<<(NN * 32 + T - 1) / T, T>>>(W2);

    // Horner on scalar channels: out = y0 + A(y1 + A(y2 + A y3)) + bias2
    {
        float* ta; float* tb; float* y0;
        cudaGetSymbolAddress((void**)&ta, g_ta);
        cudaGetSymbolAddress((void**)&tb, g_tb);
        cudaGetSymbolAddress((void**)&y0, g_y);
        float* y1 = y0 + NN; float* y2 = y1 + NN; float* y3 = y2 + NN;
        int bn = (NN + T - 1) / T;
        k_shop<<<bn, T>>>(tb, y2, y3, nullptr);
        k_shop<<<bn, T>>>(ta, y1, tb, nullptr);
        k_shop<<<bn, T>>>(out, y0, ta, bias2);
    }
    (void)in_sizes; (void)n_in; (void)out_size;
}

// round 3
// speedup vs baseline: 1.9691x; 1.3258x over previous
#include <cuda_runtime.h>

#define NN   100000
#define EE   1600000
#define DINF 67
#define DPAD 68          // padded feature width (17 * float4)
#define DH   128
#define KTOT 272         // 4 * DPAD
#define NCH  17          // float4 chunks per row
#define SCAN_B 1024
#define NBLK   98        // ceil(100000/1024)

// ---------------- scratch (static device memory; no allocs allowed) ----------
__device__ float g_hbuf[4][NN * DPAD];      // hop buffers h0..h3 (padded)
__device__ int   g_degi[NN];
__device__ float g_dis[NN];
__device__ int   g_off[NN + 1];             // CSC offsets
__device__ int   g_cursor[NN];
__device__ int   g_blocksum[NBLK + 1];
__device__ int   g_csc_src[EE];             // source node per CSC slot
__device__ float g_csc_w[EE];               // normalized weight per CSC slot
__device__ float g_Wcat[KTOT * DH];         // padded/transposed W1
__device__ float g_A1[DINF], g_B1[DINF];    // BN1 folded affine
__device__ float g_A2[DH],   g_B2[DH];      // BN2 + bias1 folded affine
__device__ float g_hmid[NN * DH];           // post layer1+BN2+lrelu
__device__ float g_y[4][NN];                // layer2 projections
__device__ float g_ta[NN], g_tb[NN];        // scalar propagation buffers

// ---------------- kernels ----------------------------------------------------
__global__ void k_zero() {
    int i = blockIdx.x * blockDim.x + threadIdx.x;
    if (i < NN) g_degi[i] = 0;
}

__global__ void k_deg(const int* __restrict__ col) {
    int e = blockIdx.x * blockDim.x + threadIdx.x;
    if (e < EE) atomicAdd(&g_degi[col[e]], 1);
}

// block-level inclusive scan -> exclusive offsets (partial) + block totals
__global__ void k_scanA() {
    __shared__ int s[SCAN_B];
    int g = blockIdx.x * SCAN_B + threadIdx.x;
    int v = (g < NN) ? g_degi[g] : 0;
    s[threadIdx.x] = v;
    __syncthreads();
#pragma unroll
    for (int d = 1; d < SCAN_B; d <<= 1) {
        int t = (threadIdx.x >= d) ? s[threadIdx.x - d] : 0;
        __syncthreads();
        s[threadIdx.x] += t;
        __syncthreads();
    }
    if (g < NN) g_off[g] = s[threadIdx.x] - v;   // exclusive within block
    if (threadIdx.x == SCAN_B - 1) g_blocksum[blockIdx.x] = s[SCAN_B - 1];
}

// parallel scan over the 98 block sums (one block, Kogge-Stone in smem)
__global__ void k_scanB() {
    __shared__ int s[128];
    int i = threadIdx.x;
    int v = (i < NBLK) ? g_blocksum[i] : 0;
    s[i] = v;
    __syncthreads();
#pragma unroll
    for (int d = 1; d < 128; d <<= 1) {
        int t = (i >= d) ? s[i - d] : 0;
        __syncthreads();
        s[i] += t;
        __syncthreads();
    }
    if (i < NBLK) g_blocksum[i] = s[i] - v;      // exclusive
    if (i == NBLK - 1) g_off[NN] = s[i];         // total == EE
}

__global__ void k_scanC() {
    int g = blockIdx.x * SCAN_B + threadIdx.x;
    if (g < NN) {
        int o = g_off[g] + g_blocksum[blockIdx.x];
        g_off[g] = o;
        g_cursor[g] = o;
        int d = g_degi[g];
        g_dis[g] = (d > 0) ? rsqrtf((float)d) : 0.f;
    }
}

__global__ void k_fill(const int* __restrict__ row, const int* __restrict__ col) {
    int e = blockIdx.x * blockDim.x + threadIdx.x;
    if (e < EE) {
        int c = col[e], r = row[e];
        int p = atomicAdd(&g_cursor[c], 1);
        g_csc_src[p] = r;
        g_csc_w[p] = g_dis[r] * g_dis[c];
    }
}

__global__ void k_setup(const float* __restrict__ g1, const float* __restrict__ b1,
                        const float* __restrict__ m1, const float* __restrict__ v1,
                        const float* __restrict__ W1, const float* __restrict__ bias1,
                        const float* __restrict__ g2, const float* __restrict__ b2,
                        const float* __restrict__ m2, const float* __restrict__ v2) {
    int i = blockIdx.x * blockDim.x + threadIdx.x;
    if (i < DINF) {
        float s = g1[i] * rsqrtf(v1[i] + 1e-5f);
        g_A1[i] = s;
        g_B1[i] = b1[i] - m1[i] * s;
    }
    if (i < DH) {
        float s = g2[i] * rsqrtf(v2[i] + 1e-5f);
        g_A2[i] = s;
        g_B2[i] = (bias1[i] - m2[i]) * s + b2[i];
    }
    if (i < KTOT * DH) {
        int j = i / DH, o = i - j * DH;
        int hop = j / DPAD, d = j - hop * DPAD;
        g_Wcat[i] = (d < DINF) ? W1[(hop * DH + o) * DINF + d] : 0.f;
    }
}

__global__ void k_bn1(const float* __restrict__ x) {
    int i = blockIdx.x * blockDim.x + threadIdx.x;
    if (i >= NN * DPAD) return;
    int n = i / DPAD, d = i - n * DPAD;
    g_hbuf[0][i] = (d < DINF) ? x[n * DINF + d] * g_A1[d] + g_B1[d] : 0.f;
}

// gather hop: dst[n] = sum_{in-edges} w * src[r], vectorized x4, no atomics
__global__ void k_hop(const float* __restrict__ src, float* __restrict__ dst) {
    int idx = blockIdx.x * blockDim.x + threadIdx.x;
    if (idx >= NN * NCH) return;
    int n = idx / NCH, c = idx - n * NCH;
    int s = g_off[n], e2 = g_off[n + 1];
    float ax = 0.f, ay = 0.f, az = 0.f, aw = 0.f;
#pragma unroll 4
    for (int i = s; i < e2; i++) {
        int r = __ldg(&g_csc_src[i]);
        float w = __ldg(&g_csc_w[i]);
        const float4 v = *reinterpret_cast<const float4*>(src + r * DPAD + c * 4);
        ax += w * v.x; ay += w * v.y; az += w * v.z; aw += w * v.w;
    }
    float4 o; o.x = ax; o.y = ay; o.z = az; o.w = aw;
    *reinterpret_cast<float4*>(dst + n * DPAD + c * 4) = o;
}

// ---------------- tf32 tensor-core GEMM --------------------------------------
// C[N,128] = [h0|h1|h2|h3] (N x 272) @ Wcat (272 x 128), fused BN2+bias1+leaky
// block: 128(M) x 128(N), 8 warps; warp tile 64x32 via mma.m16n8k8.tf32
__device__ __forceinline__ unsigned f2tf32(float f) {
    unsigned u;
    asm("cvt.rna.tf32.f32 %0, %1;" : "=r"(u) : "f"(f));
    return u;
}

__global__ void __launch_bounds__(256) k_gemm() {
    __shared__ unsigned As[8][132];   // [k][m]
    __shared__ unsigned Bs[8][132];   // [k][n]
    const int bm   = blockIdx.x * 128;
    const int tid  = threadIdx.x;
    const int lane = tid & 31;
    const int warp = tid >> 5;
    const int wm   = (warp & 1) * 64;    // warp m-offset
    const int wn   = (warp >> 1) * 32;   // warp n-offset
    const int gr   = lane >> 2;          // 0..7
    const int ct   = lane & 3;           // 0..3

    float acc[4][4][4];
#pragma unroll
    for (int s = 0; s < 4; s++)
#pragma unroll
        for (int t = 0; t < 4; t++)
#pragma unroll
            for (int r = 0; r < 4; r++) acc[s][t][r] = 0.f;

    for (int k0 = 0; k0 < KTOT; k0 += 8) {
        // load A tile: 128 rows x 8 k (1024 elems by 256 threads)
#pragma unroll
        for (int l = 0; l < 4; l++) {
            int li = tid + l * 256;
            int m = li >> 3, kk = li & 7;
            int n = bm + m;
            int j = k0 + kk;
            int hop = j / DPAD, d = j - hop * DPAD;
            float v = (n < NN) ? g_hbuf[hop][n * DPAD + d] : 0.f;
            As[kk][m] = f2tf32(v);
        }
        // load B tile: 8 k x 128 n
#pragma unroll
        for (int l = 0; l < 4; l++) {
            int li = tid + l * 256;
            int kk = li >> 7, o = li & 127;
            Bs[kk][o] = f2tf32(g_Wcat[(k0 + kk) * DH + o]);
        }
        __syncthreads();

        // B fragments: b[t][0..1]
        unsigned bf[4][2];
#pragma unroll
        for (int t = 0; t < 4; t++) {
            int ncol = wn + t * 8 + gr;
            bf[t][0] = Bs[ct][ncol];
            bf[t][1] = Bs[ct + 4][ncol];
        }
#pragma unroll
        for (int s = 0; s < 4; s++) {
            int mrow = wm + s * 16 + gr;
            unsigned a0 = As[ct][mrow];
            unsigned a1 = As[ct][mrow + 8];
            unsigned a2 = As[ct + 4][mrow];
            unsigned a3 = As[ct + 4][mrow + 8];
#pragma unroll
            for (int t = 0; t < 4; t++) {
                asm volatile(
                    "mma.sync.aligned.m16n8k8.row.col.f32.tf32.tf32.f32 "
                    "{%0,%1,%2,%3}, {%4,%5,%6,%7}, {%8,%9}, {%0,%1,%2,%3};"
                    : "+f"(acc[s][t][0]), "+f"(acc[s][t][1]),
                      "+f"(acc[s][t][2]), "+f"(acc[s][t][3])
                    : "r"(a0), "r"(a1), "r"(a2), "r"(a3),
                      "r"(bf[t][0]), "r"(bf[t][1]));
            }
        }
        __syncthreads();
    }

    // epilogue: BN2 + bias1 + leaky relu, store hmid
#pragma unroll
    for (int s = 0; s < 4; s++) {
        int r0 = bm + wm + s * 16 + gr;       // rows r0, r0+8
#pragma unroll
        for (int t = 0; t < 4; t++) {
            int c0 = wn + t * 8 + 2 * ct;     // cols c0, c0+1
#pragma unroll
            for (int r = 0; r < 4; r++) {
                int nrow = r0 + ((r >= 2) ? 8 : 0);
                int o = c0 + (r & 1);
                if (nrow < NN) {
                    float v = acc[s][t][r] * g_A2[o] + g_B2[o];
                    v = (v > 0.f) ? v : 0.01f * v;
                    g_hmid[nrow * DH + o] = v;
                }
            }
        }
    }
}

// y[k][n] = dot(hmid[n,:], W2[k][0][:]) ; one warp per node
__global__ void k_y(const float* __restrict__ W2) {
    int gt = blockIdx.x * blockDim.x + threadIdx.x;
    int lane = gt & 31, warp = gt >> 5;
    int nwarps = (gridDim.x * blockDim.x) >> 5;
    float4 w0 = *reinterpret_cast<const float4*>(W2 + 0 * DH + lane * 4);
    float4 w1 = *reinterpret_cast<const float4*>(W2 + 1 * DH + lane * 4);
    float4 w2 = *reinterpret_cast<const float4*>(W2 + 2 * DH + lane * 4);
    float4 w3 = *reinterpret_cast<const float4*>(W2 + 3 * DH + lane * 4);
    for (int n = warp; n < NN; n += nwarps) {
        float4 h = *reinterpret_cast<const float4*>(g_hmid + n * DH + lane * 4);
        float s0 = h.x * w0.x + h.y * w0.y + h.z * w0.z + h.w * w0.w;
        float s1 = h.x * w1.x + h.y * w1.y + h.z * w1.z + h.w * w1.w;
        float s2 = h.x * w2.x + h.y * w2.y + h.z * w2.z + h.w * w2.w;
        float s3 = h.x * w3.x + h.y * w3.y + h.z * w3.z + h.w * w3.w;
#pragma unroll
        for (int off = 16; off > 0; off >>= 1) {
            s0 += __shfl_xor_sync(0xFFFFFFFFu, s0, off);
            s1 += __shfl_xor_sync(0xFFFFFFFFu, s1, off);
            s2 += __shfl_xor_sync(0xFFFFFFFFu, s2, off);
            s3 += __shfl_xor_sync(0xFFFFFFFFu, s3, off);
        }
        if (lane == 0) {
            g_y[0][n] = s0; g_y[1][n] = s1; g_y[2][n] = s2; g_y[3][n] = s3;
        }
    }
}

// scalar gather hop: dst[n] = addin[n] (+bias) + sum w*src[r]
__global__ void k_shop(float* __restrict__ dst, const float* __restrict__ addin,
                       const float* __restrict__ src, const float* __restrict__ bias) {
    int n = blockIdx.x * blockDim.x + threadIdx.x;
    if (n >= NN) return;
    float acc = addin[n] + (bias ? bias[0] : 0.f);
    int e2 = g_off[n + 1];
#pragma unroll 4
    for (int i = g_off[n]; i < e2; i++)
        acc += g_csc_w[i] * src[g_csc_src[i]];
    dst[n] = acc;
}

// ---------------- launch -----------------------------------------------------
extern "C" void kernel_launch(void* const* d_in, const int* in_sizes, int n_in,
                              void* d_out, int out_size) {
    const float* x     = (const float*)d_in[0];
    const int*   ei    = (const int*)  d_in[1];
    const float* g1    = (const float*)d_in[2];
    const float* b1    = (const float*)d_in[3];
    const float* m1    = (const float*)d_in[4];
    const float* v1    = (const float*)d_in[5];
    const float* W1    = (const float*)d_in[6];
    const float* bias1 = (const float*)d_in[7];
    const float* g2    = (const float*)d_in[8];
    const float* b2    = (const float*)d_in[9];
    const float* m2    = (const float*)d_in[10];
    const float* v2    = (const float*)d_in[11];
    const float* W2    = (const float*)d_in[12];
    const float* bias2 = (const float*)d_in[13];
    float* out = (float*)d_out;

    const int* row = ei;
    const int* col = ei + EE;

    const int T = 256;

    // CSC build
    k_zero<<<(NN + T - 1) / T, T>>>();
    k_deg<<<(EE + T - 1) / T, T>>>(col);
    k_scanA<<<NBLK, SCAN_B>>>();
    k_scanB<<<1, 128>>>();
    k_scanC<<<NBLK, SCAN_B>>>();
    k_fill<<<(EE + T - 1) / T, T>>>(row, col);

    k_setup<<<(KTOT * DH + T - 1) / T, T>>>(g1, b1, m1, v1, W1, bias1, g2, b2, m2, v2);
    k_bn1<<<(NN * DPAD + T - 1) / T, T>>>(x);

    // layer-1 propagation: 3 gather hops at width 68
    {
        float* h0; float* h1; float* h2; float* h3;
        cudaGetSymbolAddress((void**)&h0, g_hbuf);
        h1 = h0 + NN * DPAD; h2 = h1 + NN * DPAD; h3 = h2 + NN * DPAD;
        int blocks = (NN * NCH + T - 1) / T;
        k_hop<<<blocks, T>>>(h0, h1);
        k_hop<<<blocks, T>>>(h1, h2);
        k_hop<<<blocks, T>>>(h2, h3);
    }

    // fused tf32 GEMM + bias1 + BN2 + leaky
    k_gemm<<<(NN + 127) / 128, 256>>>();

    // layer-2 projections to 4 scalar channels
    k_y<<<(NN * 32 + T - 1) / T, T>>>(W2);

    // Horner on scalar channels: out = y0 + A(y1 + A(y2 + A y3)) + bias2
    {
        float* ta; float* tb; float* y0;
        cudaGetSymbolAddress((void**)&ta, g_ta);
        cudaGetSymbolAddress((void**)&tb, g_tb);
        cudaGetSymbolAddress((void**)&y0, g_y);
        float* y1 = y0 + NN; float* y2 = y1 + NN; float* y3 = y2 + NN;
        int bn = (NN + T - 1) / T;
        k_shop<<<bn, T>>>(tb, y2, y3, nullptr);
        k_shop<<<bn, T>>>(ta, y1, tb, nullptr);
        k_shop<<<bn, T>>>(out, y0, ta, bias2);
    }
    (void)in_sizes; (void)n_in; (void)out_size;
}

// round 5
// speedup vs baseline: 2.7960x; 1.4199x over previous
#include <cuda_runtime.h>
#include <cuda_fp16.h>

#define NN   100000
#define EE   1600000
#define DINF 67
#define DPAD 68          // padded feature width in halves (34 half2)
#define DH   128
#define KTOT 272         // 4 * DPAD (halves)
#define KU   136         // KTOT/2 (uints per Wcat row)
#define SCAN_B 1024
#define NBLK   98        // ceil(100000/1024)

// ---------------- scratch (static device memory; no allocs allowed) ----------
__device__ __half g_hbufH[4 * NN * DPAD];   // hop buffers h0..h3, fp16
__device__ int    g_degi[NN];
__device__ float  g_dis[NN];
__device__ int    g_off[NN + 1];            // CSC offsets
__device__ int    g_cursor[NN];
__device__ int    g_blocksum[NBLK + 1];
__device__ int2   g_csc[EE];                // packed (src, weight-bits)
__device__ __half g_WcatH[DH * KTOT];       // W1 transposed [o][j], fp16
__device__ float  g_A1[DINF], g_B1[DINF];   // BN1 folded affine
__device__ float  g_A2[DH],   g_B2[DH];     // BN2 + bias1 folded affine
__device__ float  g_y[4][NN];               // layer2 projections
__device__ float  g_ta[NN], g_tb[NN];       // scalar propagation buffers

// ---------------- CSC build ---------------------------------------------------
__global__ void k_zero() {
    int i = blockIdx.x * blockDim.x + threadIdx.x;
    if (i < NN) g_degi[i] = 0;
}

__global__ void k_deg(const int* __restrict__ col) {
    int e = blockIdx.x * blockDim.x + threadIdx.x;
    if (e < EE) atomicAdd(&g_degi[col[e]], 1);
}

// block-level inclusive scan -> exclusive offsets (partial) + block totals
__global__ void k_scanA() {
    __shared__ int s[SCAN_B];
    int g = blockIdx.x * SCAN_B + threadIdx.x;
    int v = (g < NN) ? g_degi[g] : 0;
    s[threadIdx.x] = v;
    __syncthreads();
#pragma unroll
    for (int d = 1; d < SCAN_B; d <<= 1) {
        int t = (threadIdx.x >= d) ? s[threadIdx.x - d] : 0;
        __syncthreads();
        s[threadIdx.x] += t;
        __syncthreads();
    }
    if (g < NN) g_off[g] = s[threadIdx.x] - v;   // exclusive within block
    if (threadIdx.x == SCAN_B - 1) g_blocksum[blockIdx.x] = s[SCAN_B - 1];
}

// merged: every block scans the 98 block sums itself, then finalizes its slice
__global__ void k_scanC() {
    __shared__ int s[128];
    int tix = threadIdx.x;
    if (tix < 128) s[tix] = (tix < NBLK) ? g_blocksum[tix] : 0;
    __syncthreads();
#pragma unroll
    for (int d = 1; d < 128; d <<= 1) {
        int t = (tix >= d && tix < 128) ? s[tix - d] : 0;
        __syncthreads();
        if (tix < 128) s[tix] += t;
        __syncthreads();
    }
    int pref = (blockIdx.x == 0) ? 0 : s[blockIdx.x - 1];
    int g = blockIdx.x * SCAN_B + tix;
    if (g < NN) {
        int o = g_off[g] + pref;
        g_off[g] = o;
        g_cursor[g] = o;
        int dg = g_degi[g];
        g_dis[g] = (dg > 0) ? rsqrtf((float)dg) : 0.f;
    }
    if (g == 0) g_off[NN] = EE;
}

__global__ void k_fill(const int* __restrict__ row, const int* __restrict__ col) {
    int e = blockIdx.x * blockDim.x + threadIdx.x;
    if (e < EE) {
        int c = col[e], r = row[e];
        int p = atomicAdd(&g_cursor[c], 1);
        int2 pk;
        pk.x = r;
        pk.y = __float_as_int(g_dis[r] * g_dis[c]);
        g_csc[p] = pk;
    }
}

// ---------------- parameter prep ---------------------------------------------
__global__ void k_setup(const float* __restrict__ g1, const float* __restrict__ b1,
                        const float* __restrict__ m1, const float* __restrict__ v1,
                        const float* __restrict__ W1, const float* __restrict__ bias1,
                        const float* __restrict__ g2, const float* __restrict__ b2,
                        const float* __restrict__ m2, const float* __restrict__ v2) {
    int i = blockIdx.x * blockDim.x + threadIdx.x;
    if (i < DINF) {
        float s = g1[i] * rsqrtf(v1[i] + 1e-5f);
        g_A1[i] = s;
        g_B1[i] = b1[i] - m1[i] * s;
    }
    if (i < DH) {
        float s = g2[i] * rsqrtf(v2[i] + 1e-5f);
        g_A2[i] = s;
        g_B2[i] = (bias1[i] - m2[i]) * s + b2[i];
    }
    if (i < KTOT * DH) {
        int j = i / DH, o = i - j * DH;
        int hop = j / DPAD, d = j - hop * DPAD;
        float w = (d < DINF) ? W1[(hop * DH + o) * DINF + d] : 0.f;
        g_WcatH[o * KTOT + j] = __float2half_rn(w);   // transposed [o][j]
    }
}

// BN1 -> h0 (fp16), half2 stores
__global__ void k_bn1(const float* __restrict__ x) {
    int i = blockIdx.x * blockDim.x + threadIdx.x;
    if (i >= NN * 34) return;
    int n = i / 34, p = i - n * 34;
    int d = 2 * p;
    float f0 = x[n * DINF + d] * g_A1[d] + g_B1[d];
    float f1 = (d + 1 < DINF) ? x[n * DINF + d + 1] * g_A1[d + 1] + g_B1[d + 1] : 0.f;
    __half2 h = __floats2half2_rn(f0, f1);
    *reinterpret_cast<__half2*>(g_hbufH + n * DPAD + d) = h;
}

// gather hop (fp16): dst[n] = sum_{in-edges} w * src[r]; 17 chunks of 4 halves
__global__ void k_hop(const __half* __restrict__ src, __half* __restrict__ dst) {
    int idx = blockIdx.x * blockDim.x + threadIdx.x;
    if (idx >= NN * 17) return;
    int n = idx / 17, c = idx - n * 17;
    int s = g_off[n], e2 = g_off[n + 1];
    float a0 = 0.f, a1 = 0.f, a2 = 0.f, a3 = 0.f;
    const char* sbase = reinterpret_cast<const char*>(src);
#pragma unroll 4
    for (int i = s; i < e2; i++) {
        int2 pk = __ldg(&g_csc[i]);
        float w = __int_as_float(pk.y);
        uint2 u = *reinterpret_cast<const uint2*>(sbase + (size_t)pk.x * 136 + c * 8);
        __half2 h0 = *reinterpret_cast<__half2*>(&u.x);
        __half2 h1 = *reinterpret_cast<__half2*>(&u.y);
        float2 f0 = __half22float2(h0);
        float2 f1 = __half22float2(h1);
        a0 += w * f0.x; a1 += w * f0.y; a2 += w * f1.x; a3 += w * f1.y;
    }
    __half2 o0 = __floats2half2_rn(a0, a1);
    __half2 o1 = __floats2half2_rn(a2, a3);
    uint2 ov;
    ov.x = *reinterpret_cast<unsigned*>(&o0);
    ov.y = *reinterpret_cast<unsigned*>(&o1);
    *reinterpret_cast<uint2*>(reinterpret_cast<char*>(dst) + (size_t)n * 136 + c * 8) = ov;
}

// ---------------- fp16 tensor-core GEMM + fused BN2/leaky + fused W2 proj ----
// hmid[N,128] = leaky(BN2([h0|h1|h2|h3] @ Wcat)); y[k][n] = hmid[n,:].W2[k]
// block 128(M) x 128(N), 8 warps, warp tile 64x32 via mma.m16n8k16.f16
__global__ void __launch_bounds__(256) k_gemm(const float* __restrict__ W2) {
    __shared__ unsigned AsU[128][9];   // [m][k-pair]
    __shared__ unsigned BsU[128][9];   // [n][k-pair]
    __shared__ float W2s[4][128];
    __shared__ float A2s[128], B2s[128];
    __shared__ float ys[4][128];

    const int bm   = blockIdx.x * 128;
    const int tid  = threadIdx.x;
    const int lane = tid & 31;
    const int warp = tid >> 5;
    const int wm   = (warp & 1) * 64;
    const int wn   = (warp >> 1) * 32;
    const int gr   = lane >> 2;          // 0..7
    const int ct   = lane & 3;           // 0..3

    // init smem params + ys
    if (tid < 128) { A2s[tid] = g_A2[tid]; B2s[tid] = g_B2[tid]; }
#pragma unroll
    for (int l = 0; l < 2; l++) {
        int li = tid + l * 256;
        if (li < 512) {
            W2s[li >> 7][li & 127] = W2[li];
            ys[li >> 7][li & 127] = 0.f;
        }
    }

    float acc[4][4][4];
#pragma unroll
    for (int s = 0; s < 4; s++)
#pragma unroll
        for (int t = 0; t < 4; t++)
#pragma unroll
            for (int r = 0; r < 4; r++) acc[s][t][r] = 0.f;

    const unsigned* hbU = reinterpret_cast<const unsigned*>(g_hbufH);
    const unsigned* wcU = reinterpret_cast<const unsigned*>(g_WcatH);

    __syncthreads();

    for (int k0h = 0; k0h < KU; k0h += 8) {   // 17 steps of k=16 halves
        // A tile: 128 m x 8 uints
#pragma unroll
        for (int l = 0; l < 4; l++) {
            int li = tid + l * 256;
            int m = li >> 3, ks = li & 7;
            int jh = k0h + ks;               // half-pair index
            int j = 2 * jh;
            int hop = j / DPAD, d = j - hop * DPAD;
            int n = bm + m;
            unsigned v = 0u;
            if (n < NN) v = hbU[hop * (NN * 34) + n * 34 + (d >> 1)];
            AsU[m][ks] = v;
        }
        // B tile: 128 n x 8 uints (Wcat already [o][j])
#pragma unroll
        for (int l = 0; l < 4; l++) {
            int li = tid + l * 256;
            int o = li >> 3, ks = li & 7;
            BsU[o][ks] = wcU[o * KU + k0h + ks];
        }
        __syncthreads();

        unsigned bf[4][2];
#pragma unroll
        for (int t = 0; t < 4; t++) {
            int col = wn + t * 8 + gr;
            bf[t][0] = BsU[col][ct];
            bf[t][1] = BsU[col][ct + 4];
        }
#pragma unroll
        for (int s = 0; s < 4; s++) {
            int mrow = wm + s * 16 + gr;
            unsigned a0 = AsU[mrow][ct];
            unsigned a1 = AsU[mrow + 8][ct];
            unsigned a2 = AsU[mrow][ct + 4];
            unsigned a3 = AsU[mrow + 8][ct + 4];
#pragma unroll
            for (int t = 0; t < 4; t++) {
                asm volatile(
                    "mma.sync.aligned.m16n8k16.row.col.f32.f16.f16.f32 "
                    "{%0,%1,%2,%3}, {%4,%5,%6,%7}, {%8,%9}, {%0,%1,%2,%3};"
                    : "+f"(acc[s][t][0]), "+f"(acc[s][t][1]),
                      "+f"(acc[s][t][2]), "+f"(acc[s][t][3])
                    : "r"(a0), "r"(a1), "r"(a2), "r"(a3),
                      "r"(bf[t][0]), "r"(bf[t][1]));
            }
        }
        __syncthreads();
    }

    // epilogue: BN2+bias1+leaky, project onto W2 channels, smem-reduce
#pragma unroll
    for (int s = 0; s < 4; s++) {
#pragma unroll
        for (int rr = 0; rr < 2; rr++) {
            int m = wm + s * 16 + gr + rr * 8;
            float p0 = 0.f, p1 = 0.f, p2 = 0.f, p3 = 0.f;
#pragma unroll
            for (int t = 0; t < 4; t++) {
#pragma unroll
                for (int cc = 0; cc < 2; cc++) {
                    int o = wn + t * 8 + 2 * ct + cc;
                    int r = rr * 2 + cc;
                    float v = acc[s][t][r] * A2s[o] + B2s[o];
                    v = (v > 0.f) ? v : 0.01f * v;
                    p0 += v * W2s[0][o];
                    p1 += v * W2s[1][o];
                    p2 += v * W2s[2][o];
                    p3 += v * W2s[3][o];
                }
            }
            atomicAdd(&ys[0][m], p0);
            atomicAdd(&ys[1][m], p1);
            atomicAdd(&ys[2][m], p2);
            atomicAdd(&ys[3][m], p3);
        }
    }
    __syncthreads();
#pragma unroll
    for (int l = 0; l < 2; l++) {
        int li = tid + l * 256;
        int ch = li >> 7, m = li & 127;
        int n = bm + m;
        if (n < NN) g_y[ch][n] = ys[ch][m];
    }
}

// scalar gather hop: dst[n] = addin[n] (+bias) + sum w*src[r]
__global__ void k_shop(float* __restrict__ dst, const float* __restrict__ addin,
                       const float* __restrict__ src, const float* __restrict__ bias) {
    int n = blockIdx.x * blockDim.x + threadIdx.x;
    if (n >= NN) return;
    float acc = addin[n] + (bias ? bias[0] : 0.f);
    int e2 = g_off[n + 1];
#pragma unroll 4
    for (int i = g_off[n]; i < e2; i++) {
        int2 pk = __ldg(&g_csc[i]);
        acc += __int_as_float(pk.y) * src[pk.x];
    }
    dst[n] = acc;
}

// ---------------- launch -----------------------------------------------------
extern "C" void kernel_launch(void* const* d_in, const int* in_sizes, int n_in,
                              void* d_out, int out_size) {
    const float* x     = (const float*)d_in[0];
    const int*   ei    = (const int*)  d_in[1];
    const float* g1    = (const float*)d_in[2];
    const float* b1    = (const float*)d_in[3];
    const float* m1    = (const float*)d_in[4];
    const float* v1    = (const float*)d_in[5];
    const float* W1    = (const float*)d_in[6];
    const float* bias1 = (const float*)d_in[7];
    const float* g2    = (const float*)d_in[8];
    const float* b2    = (const float*)d_in[9];
    const float* m2    = (const float*)d_in[10];
    const float* v2    = (const float*)d_in[11];
    const float* W2    = (const float*)d_in[12];
    const float* bias2 = (const float*)d_in[13];
    float* out = (float*)d_out;

    const int* row = ei;
    const int* col = ei + EE;

    const int T = 256;

    // CSC build
    k_zero<<<(NN + T - 1) / T, T>>>();
    k_deg<<<(EE + T - 1) / T, T>>>(col);
    k_scanA<<<NBLK, SCAN_B>>>();
    k_scanC<<<NBLK, SCAN_B>>>();
    k_fill<<<(EE + T - 1) / T, T>>>(row, col);

    k_setup<<<(KTOT * DH + T - 1) / T, T>>>(g1, b1, m1, v1, W1, bias1, g2, b2, m2, v2);
    k_bn1<<<(NN * 34 + T - 1) / T, T>>>(x);

    // layer-1 propagation: 3 gather hops at fp16 width 68
    {
        __half* h0;
        cudaGetSymbolAddress((void**)&h0, g_hbufH);
        __half* h1 = h0 + NN * DPAD;
        __half* h2 = h1 + NN * DPAD;
        __half* h3 = h2 + NN * DPAD;
        int blocks = (NN * 17 + T - 1) / T;
        k_hop<<<blocks, T>>>(h0, h1);
        k_hop<<<blocks, T>>>(h1, h2);
        k_hop<<<blocks, T>>>(h2, h3);
    }

    // fused fp16 GEMM + BN2 + leaky + W2 projection (produces g_y directly)
    k_gemm<<<(NN + 127) / 128, 256>>>(W2);

    // Horner on scalar channels: out = y0 + A(y1 + A(y2 + A y3)) + bias2
    {
        float* ta; float* tb; float* y0;
        cudaGetSymbolAddress((void**)&ta, g_ta);
        cudaGetSymbolAddress((void**)&tb, g_tb);
        cudaGetSymbolAddress((void**)&y0, g_y);
        float* y1 = y0 + NN; float* y2 = y1 + NN; float* y3 = y2 + NN;
        int bn = (NN + T - 1) / T;
        k_shop<<<bn, T>>>(tb, y2, y3, nullptr);
        k_shop<<<bn, T>>>(ta, y1, tb, nullptr);
        k_shop<<<bn, T>>>(out, y0, ta, bias2);
    }
    (void)in_sizes; (void)n_in; (void)out_size;
}

// round 6
// speedup vs baseline: 2.8504x; 1.0195x over previous
#include <cuda_runtime.h>
#include <cuda_fp16.h>

#define NN   100000
#define EE   1600000
#define DINF 67
#define DPAD 72          // padded feature width in halves (9 x uint4)
#define ROWB 144         // bytes per hop-row
#define NRU  36          // uints per hop-row
#define NG   9           // uint4 groups per hop-row
#define DH   128
#define KTOT 288         // 4 * DPAD halves
#define KU   144         // uints per Wcat row
#define NSTEP 18         // GEMM k-steps (8 uints each)
#define SCAN_B 1024
#define NBLK   98        // ceil(100000/1024)

// ---------------- scratch (static device memory; no allocs allowed) ----------
__device__ __align__(16) __half g_hbufH[4 * NN * DPAD]; // hop buffers h0..h3
__device__ int    g_degi[NN];
__device__ float  g_dis[NN];
__device__ int    g_off[NN + 1];            // CSC offsets
__device__ int    g_cursor[NN];
__device__ int    g_blocksum[NBLK + 1];
__device__ int2   g_csc[EE];                // packed (src, weight-bits)
__device__ __align__(16) __half g_WcatH[DH * KTOT];  // W1 transposed [o][j]
__device__ float  g_A1[DINF], g_B1[DINF];   // BN1 folded affine
__device__ float  g_A2[DH],   g_B2[DH];     // BN2 + bias1 folded affine
__device__ float  g_y[4][NN];               // layer2 projections
__device__ float  g_ta[NN], g_tb[NN];       // scalar propagation buffers

// ---------------- CSC build ---------------------------------------------------
__global__ void k_zero() {
    int i = blockIdx.x * blockDim.x + threadIdx.x;
    if (i < NN) g_degi[i] = 0;
}

__global__ void k_deg(const int* __restrict__ col) {
    int e = blockIdx.x * blockDim.x + threadIdx.x;
    if (e < EE) atomicAdd(&g_degi[col[e]], 1);
}

__global__ void k_scanA() {
    __shared__ int s[SCAN_B];
    int g = blockIdx.x * SCAN_B + threadIdx.x;
    int v = (g < NN) ? g_degi[g] : 0;
    s[threadIdx.x] = v;
    __syncthreads();
#pragma unroll
    for (int d = 1; d < SCAN_B; d <<= 1) {
        int t = (threadIdx.x >= d) ? s[threadIdx.x - d] : 0;
        __syncthreads();
        s[threadIdx.x] += t;
        __syncthreads();
    }
    if (g < NN) g_off[g] = s[threadIdx.x] - v;
    if (threadIdx.x == SCAN_B - 1) g_blocksum[blockIdx.x] = s[SCAN_B - 1];
}

// merged: every block scans the 98 block sums itself, then finalizes its slice
__global__ void k_scanC() {
    __shared__ int s[128];
    int tix = threadIdx.x;
    if (tix < 128) s[tix] = (tix < NBLK) ? g_blocksum[tix] : 0;
    __syncthreads();
#pragma unroll
    for (int d = 1; d < 128; d <<= 1) {
        int t = (tix >= d && tix < 128) ? s[tix - d] : 0;
        __syncthreads();
        if (tix < 128) s[tix] += t;
        __syncthreads();
    }
    int pref = (blockIdx.x == 0) ? 0 : s[blockIdx.x - 1];
    int g = blockIdx.x * SCAN_B + tix;
    if (g < NN) {
        int o = g_off[g] + pref;
        g_off[g] = o;
        g_cursor[g] = o;
        int dg = g_degi[g];
        g_dis[g] = (dg > 0) ? rsqrtf((float)dg) : 0.f;
    }
    if (g == 0) g_off[NN] = EE;
}

__global__ void k_fill(const int* __restrict__ row, const int* __restrict__ col) {
    int e = blockIdx.x * blockDim.x + threadIdx.x;
    if (e < EE) {
        int c = col[e], r = row[e];
        int p = atomicAdd(&g_cursor[c], 1);
        int2 pk;
        pk.x = r;
        pk.y = __float_as_int(g_dis[r] * g_dis[c]);
        g_csc[p] = pk;
    }
}

// ---------------- parameter prep ---------------------------------------------
__global__ void k_setup(const float* __restrict__ g1, const float* __restrict__ b1,
                        const float* __restrict__ m1, const float* __restrict__ v1,
                        const float* __restrict__ W1, const float* __restrict__ bias1,
                        const float* __restrict__ g2, const float* __restrict__ b2,
                        const float* __restrict__ m2, const float* __restrict__ v2) {
    int i = blockIdx.x * blockDim.x + threadIdx.x;
    if (i < DINF) {
        float s = g1[i] * rsqrtf(v1[i] + 1e-5f);
        g_A1[i] = s;
        g_B1[i] = b1[i] - m1[i] * s;
    }
    if (i < DH) {
        float s = g2[i] * rsqrtf(v2[i] + 1e-5f);
        g_A2[i] = s;
        g_B2[i] = (bias1[i] - m2[i]) * s + b2[i];
    }
    if (i < KTOT * DH) {
        int j = i / DH, o = i - j * DH;
        int hop = j / DPAD, d = j - hop * DPAD;
        float w = (d < DINF) ? W1[(hop * DH + o) * DINF + d] : 0.f;
        g_WcatH[o * KTOT + j] = __float2half_rn(w);   // transposed [o][j]
    }
}

// BN1 -> h0 (fp16), half2 stores; pad lanes 67..71 = 0
__global__ void k_bn1(const float* __restrict__ x) {
    int i = blockIdx.x * blockDim.x + threadIdx.x;
    if (i >= NN * NRU) return;
    int n = i / NRU, p = i - n * NRU;
    int d = 2 * p;
    float f0 = (d < DINF) ? x[n * DINF + d] * g_A1[d] + g_B1[d] : 0.f;
    float f1 = (d + 1 < DINF) ? x[n * DINF + d + 1] * g_A1[d + 1] + g_B1[d + 1] : 0.f;
    __half2 h = __floats2half2_rn(f0, f1);
    *reinterpret_cast<__half2*>(g_hbufH + (size_t)n * DPAD + d) = h;
}

// gather hop (fp16): dst[n] = sum_{in-edges} w * src[r]; 9 chunks of 16B
__global__ void k_hop(const __half* __restrict__ src, __half* __restrict__ dst) {
    int idx = blockIdx.x * blockDim.x + threadIdx.x;
    if (idx >= NN * NG) return;
    int n = idx / NG, c = idx - n * NG;
    int s = g_off[n], e2 = g_off[n + 1];
    float a0 = 0.f, a1 = 0.f, a2 = 0.f, a3 = 0.f;
    float a4 = 0.f, a5 = 0.f, a6 = 0.f, a7 = 0.f;
    const char* sbase = reinterpret_cast<const char*>(src);
#pragma unroll 4
    for (int i = s; i < e2; i++) {
        int2 pk = __ldg(&g_csc[i]);
        float w = __int_as_float(pk.y);
        uint4 u = *reinterpret_cast<const uint4*>(sbase + (size_t)pk.x * ROWB + c * 16);
        float2 f0 = __half22float2(*reinterpret_cast<__half2*>(&u.x));
        float2 f1 = __half22float2(*reinterpret_cast<__half2*>(&u.y));
        float2 f2 = __half22float2(*reinterpret_cast<__half2*>(&u.z));
        float2 f3 = __half22float2(*reinterpret_cast<__half2*>(&u.w));
        a0 += w * f0.x; a1 += w * f0.y; a2 += w * f1.x; a3 += w * f1.y;
        a4 += w * f2.x; a5 += w * f2.y; a6 += w * f3.x; a7 += w * f3.y;
    }
    __half2 o0 = __floats2half2_rn(a0, a1);
    __half2 o1 = __floats2half2_rn(a2, a3);
    __half2 o2 = __floats2half2_rn(a4, a5);
    __half2 o3 = __floats2half2_rn(a6, a7);
    uint4 ov;
    ov.x = *reinterpret_cast<unsigned*>(&o0);
    ov.y = *reinterpret_cast<unsigned*>(&o1);
    ov.z = *reinterpret_cast<unsigned*>(&o2);
    ov.w = *reinterpret_cast<unsigned*>(&o3);
    *reinterpret_cast<uint4*>(reinterpret_cast<char*>(dst) + (size_t)n * ROWB + c * 16) = ov;
}

// ---------------- fp16 tensor-core GEMM, cp.async 2-stage pipeline -----------
// hmid = leaky(BN2([h0|h1|h2|h3] @ Wcat)); y[k][n] = hmid[n,:].W2[k] (fused)
__device__ __forceinline__ void cp16(unsigned sdst, const void* gsrc, int sz) {
    asm volatile("cp.async.cg.shared.global [%0], [%1], 16, %2;"
                 :: "r"(sdst), "l"(gsrc), "r"(sz));
}

__global__ void __launch_bounds__(256) k_gemm(const float* __restrict__ W2) {
    __shared__ unsigned As[2][128][8];   // [stage][m][k-uint]
    __shared__ unsigned Bs[2][128][8];   // [stage][n][k-uint]
    __shared__ float W2s[4][128];
    __shared__ float A2s[128], B2s[128];
    __shared__ float ys[4][128];

    const int bm   = blockIdx.x * 128;
    const int tid  = threadIdx.x;
    const int lane = tid & 31;
    const int warp = tid >> 5;
    const int wm   = (warp & 1) * 64;
    const int wn   = (warp >> 1) * 32;
    const int gr   = lane >> 2;          // 0..7
    const int ct   = lane & 3;           // 0..3

    if (tid < 128) { A2s[tid] = g_A2[tid]; B2s[tid] = g_B2[tid]; }
#pragma unroll
    for (int l = 0; l < 2; l++) {
        int li = tid + l * 256;
        if (li < 512) {
            W2s[li >> 7][li & 127] = W2[li];
            ys[li >> 7][li & 127] = 0.f;
        }
    }

    float acc[4][4][4];
#pragma unroll
    for (int s = 0; s < 4; s++)
#pragma unroll
        for (int t = 0; t < 4; t++)
#pragma unroll
            for (int r = 0; r < 4; r++) acc[s][t][r] = 0.f;

    const uint4* hb4 = reinterpret_cast<const uint4*>(g_hbufH);
    const uint4* wc4 = reinterpret_cast<const uint4*>(g_WcatH);

    const int mro  = tid >> 1;          // row (A) / out-col (B) this thread copies
    const int gsel = tid & 1;           // which 16B group within the k-step
    const int an   = bm + mro;
    const int asz  = (an < NN) ? 16 : 0;
    const int anc  = (an < NN) ? an : 0;   // clamped address

    // prefetch helper (stage st, k-step s)
    auto prefetch = [&](int st, int s) {
        int G = 2 * s + gsel;               // uint4 group index within full row
        int hop = G / NG, off = G - hop * NG;
        unsigned ad = (unsigned)__cvta_generic_to_shared(&As[st][mro][gsel * 4]);
        cp16(ad, hb4 + (size_t)hop * (NN * NG) + (size_t)anc * NG + off, asz);
        unsigned bd = (unsigned)__cvta_generic_to_shared(&Bs[st][mro][gsel * 4]);
        cp16(bd, wc4 + (size_t)mro * NG * 4 + G, 16);
    };

    prefetch(0, 0);
    asm volatile("cp.async.commit_group;" ::: "memory");

    for (int s = 0; s < NSTEP; s++) {
        int st = s & 1;
        if (s + 1 < NSTEP) {
            prefetch(st ^ 1, s + 1);
            asm volatile("cp.async.commit_group;" ::: "memory");
            asm volatile("cp.async.wait_group 1;" ::: "memory");
        } else {
            asm volatile("cp.async.wait_group 0;" ::: "memory");
        }
        __syncthreads();

        unsigned bf[4][2];
#pragma unroll
        for (int t = 0; t < 4; t++) {
            int col = wn + t * 8 + gr;
            bf[t][0] = Bs[st][col][ct];
            bf[t][1] = Bs[st][col][ct + 4];
        }
#pragma unroll
        for (int si = 0; si < 4; si++) {
            int mrow = wm + si * 16 + gr;
            unsigned a0 = As[st][mrow][ct];
            unsigned a1 = As[st][mrow + 8][ct];
            unsigned a2 = As[st][mrow][ct + 4];
            unsigned a3 = As[st][mrow + 8][ct + 4];
#pragma unroll
            for (int t = 0; t < 4; t++) {
                asm volatile(
                    "mma.sync.aligned.m16n8k16.row.col.f32.f16.f16.f32 "
                    "{%0,%1,%2,%3}, {%4,%5,%6,%7}, {%8,%9}, {%0,%1,%2,%3};"
                    : "+f"(acc[si][t][0]), "+f"(acc[si][t][1]),
                      "+f"(acc[si][t][2]), "+f"(acc[si][t][3])
                    : "r"(a0), "r"(a1), "r"(a2), "r"(a3),
                      "r"(bf[t][0]), "r"(bf[t][1]));
            }
        }
        __syncthreads();
    }

    // epilogue: BN2+bias1+leaky, project onto W2 channels, smem-reduce
#pragma unroll
    for (int s = 0; s < 4; s++) {
#pragma unroll
        for (int rr = 0; rr < 2; rr++) {
            int m = wm + s * 16 + gr + rr * 8;
            float p0 = 0.f, p1 = 0.f, p2 = 0.f, p3 = 0.f;
#pragma unroll
            for (int t = 0; t < 4; t++) {
#pragma unroll
                for (int cc = 0; cc < 2; cc++) {
                    int o = wn + t * 8 + 2 * ct + cc;
                    int r = rr * 2 + cc;
                    float v = acc[s][t][r] * A2s[o] + B2s[o];
                    v = (v > 0.f) ? v : 0.01f * v;
                    p0 += v * W2s[0][o];
                    p1 += v * W2s[1][o];
                    p2 += v * W2s[2][o];
                    p3 += v * W2s[3][o];
                }
            }
            atomicAdd(&ys[0][m], p0);
            atomicAdd(&ys[1][m], p1);
            atomicAdd(&ys[2][m], p2);
            atomicAdd(&ys[3][m], p3);
        }
    }
    __syncthreads();
#pragma unroll
    for (int l = 0; l < 2; l++) {
        int li = tid + l * 256;
        int ch = li >> 7, m = li & 127;
        int n = bm + m;
        if (n < NN) g_y[ch][n] = ys[ch][m];
    }
}

// scalar gather hop: dst[n] = addin[n] (+bias) + sum w*src[r]
__global__ void k_shop(float* __restrict__ dst, const float* __restrict__ addin,
                       const float* __restrict__ src, const float* __restrict__ bias) {
    int n = blockIdx.x * blockDim.x + threadIdx.x;
    if (n >= NN) return;
    float acc = addin[n] + (bias ? bias[0] : 0.f);
    int e2 = g_off[n + 1];
#pragma unroll 4
    for (int i = g_off[n]; i < e2; i++) {
        int2 pk = __ldg(&g_csc[i]);
        acc += __int_as_float(pk.y) * src[pk.x];
    }
    dst[n] = acc;
}

// ---------------- launch -----------------------------------------------------
extern "C" void kernel_launch(void* const* d_in, const int* in_sizes, int n_in,
                              void* d_out, int out_size) {
    const float* x     = (const float*)d_in[0];
    const int*   ei    = (const int*)  d_in[1];
    const float* g1    = (const float*)d_in[2];
    const float* b1    = (const float*)d_in[3];
    const float* m1    = (const float*)d_in[4];
    const float* v1    = (const float*)d_in[5];
    const float* W1    = (const float*)d_in[6];
    const float* bias1 = (const float*)d_in[7];
    const float* g2    = (const float*)d_in[8];
    const float* b2    = (const float*)d_in[9];
    const float* m2    = (const float*)d_in[10];
    const float* v2    = (const float*)d_in[11];
    const float* W2    = (const float*)d_in[12];
    const float* bias2 = (const float*)d_in[13];
    float* out = (float*)d_out;

    const int* row = ei;
    const int* col = ei + EE;

    const int T = 256;

    // CSC build
    k_zero<<<(NN + T - 1) / T, T>>>();
    k_deg<<<(EE + T - 1) / T, T>>>(col);
    k_scanA<<<NBLK, SCAN_B>>>();
    k_scanC<<<NBLK, SCAN_B>>>();
    k_fill<<<(EE + T - 1) / T, T>>>(row, col);

    k_setup<<<(KTOT * DH + T - 1) / T, T>>>(g1, b1, m1, v1, W1, bias1, g2, b2, m2, v2);
    k_bn1<<<(NN * NRU + T - 1) / T, T>>>(x);

    // layer-1 propagation: 3 gather hops at fp16 width 72
    {
        __half* h0;
        cudaGetSymbolAddress((void**)&h0, g_hbufH);
        __half* h1 = h0 + (size_t)NN * DPAD;
        __half* h2 = h1 + (size_t)NN * DPAD;
        __half* h3 = h2 + (size_t)NN * DPAD;
        int blocks = (NN * NG + T - 1) / T;
        k_hop<<<blocks, T>>>(h0, h1);
        k_hop<<<blocks, T>>>(h1, h2);
        k_hop<<<blocks, T>>>(h2, h3);
    }

    // fused fp16 GEMM + BN2 + leaky + W2 projection (produces g_y directly)
    k_gemm<<<(NN + 127) / 128, 256>>>(W2);

    // Horner on scalar channels: out = y0 + A(y1 + A(y2 + A y3)) + bias2
    {
        float* ta; float* tb; float* y0;
        cudaGetSymbolAddress((void**)&ta, g_ta);
        cudaGetSymbolAddress((void**)&tb, g_tb);
        cudaGetSymbolAddress((void**)&y0, g_y);
        float* y1 = y0 + NN; float* y2 = y1 + NN; float* y3 = y2 + NN;
        int bn = (NN + T - 1) / T;
        k_shop<<<bn, T>>>(tb, y2, y3, nullptr);
        k_shop<<<bn, T>>>(ta, y1, tb, nullptr);
        k_shop<<<bn, T>>>(out, y0, ta, bias2);
    }
    (void)in_sizes; (void)n_in; (void)out_size;
}

// round 8
// speedup vs baseline: 2.8739x; 1.0082x over previous
#include <cuda_runtime.h>
#include <cuda_fp16.h>

#define NN   100000
#define EE   1600000
#define DINF 67
#define DPAD 72          // padded feature width in halves (9 x uint4)
#define ROWB 144         // bytes per hop-row
#define NRU  36          // half2 pairs per hop-row
#define NG   9           // uint4 groups per hop-row
#define DH   128
#define KTOT 288         // 4 * DPAD halves
#define NSTEP 18         // GEMM k-steps (8 uints each)
#define SCAN_B 1024
#define NBLK   98        // ceil(100000/1024)

// ---------------- scratch (static device memory; no allocs allowed) ----------
__device__ __align__(16) __half g_hbufH[4 * NN * DPAD]; // hop buffers h0..h3
__device__ int    g_degi[NN];
__device__ float  g_dis[NN];
__device__ int    g_off[NN + 1];            // CSC offsets
__device__ int    g_cursor[NN];
__device__ int    g_blocksum[NBLK + 1];
__device__ __align__(16) int2 g_csc[EE];    // packed (src, half2(w,w) bits)
__device__ __align__(16) __half g_WcatH[DH * KTOT];  // W1 transposed [o][j]
__device__ float  g_A1[DINF], g_B1[DINF];   // BN1 folded affine
__device__ float  g_A2[DH],   g_B2[DH];     // BN2 + bias1 folded affine
__device__ float  g_y[4][NN];               // layer2 projections
__device__ float  g_ta[NN], g_tb[NN];       // scalar propagation buffers

// ---------------- CSC build ---------------------------------------------------
__global__ void k_zero() {
    int i = blockIdx.x * blockDim.x + threadIdx.x;
    if (i < NN) g_degi[i] = 0;
}

__global__ void k_deg(const int* __restrict__ col) {
    int e = blockIdx.x * blockDim.x + threadIdx.x;
    if (e < EE) atomicAdd(&g_degi[col[e]], 1);
}

__global__ void k_scanA() {
    __shared__ int s[SCAN_B];
    int g = blockIdx.x * SCAN_B + threadIdx.x;
    int v = (g < NN) ? g_degi[g] : 0;
    s[threadIdx.x] = v;
    __syncthreads();
#pragma unroll
    for (int d = 1; d < SCAN_B; d <<= 1) {
        int t = (threadIdx.x >= d) ? s[threadIdx.x - d] : 0;
        __syncthreads();
        s[threadIdx.x] += t;
        __syncthreads();
    }
    if (g < NN) g_off[g] = s[threadIdx.x] - v;
    if (threadIdx.x == SCAN_B - 1) g_blocksum[blockIdx.x] = s[SCAN_B - 1];
}

// merged: every block scans the 98 block sums itself, then finalizes its slice
__global__ void k_scanC() {
    __shared__ int s[128];
    int tix = threadIdx.x;
    if (tix < 128) s[tix] = (tix < NBLK) ? g_blocksum[tix] : 0;
    __syncthreads();
#pragma unroll
    for (int d = 1; d < 128; d <<= 1) {
        int t = (tix >= d && tix < 128) ? s[tix - d] : 0;
        __syncthreads();
        if (tix < 128) s[tix] += t;
        __syncthreads();
    }
    int pref = (blockIdx.x == 0) ? 0 : s[blockIdx.x - 1];
    int g = blockIdx.x * SCAN_B + tix;
    if (g < NN) {
        int o = g_off[g] + pref;
        g_off[g] = o;
        g_cursor[g] = o;
        int dg = g_degi[g];
        g_dis[g] = (dg > 0) ? rsqrtf((float)dg) : 0.f;
    }
    if (g == 0) g_off[NN] = EE;
}

__global__ void k_fill(const int* __restrict__ row, const int* __restrict__ col) {
    int e = blockIdx.x * blockDim.x + threadIdx.x;
    if (e < EE) {
        int c = col[e], r = row[e];
        int p = atomicAdd(&g_cursor[c], 1);
        float w = g_dis[r] * g_dis[c];
        unsigned hw = __half_as_ushort(__float2half_rn(w));
        int2 pk;
        pk.x = r;
        pk.y = (int)(hw | (hw << 16));   // half2(w, w) bit pattern
        g_csc[p] = pk;
    }
}

// ---------------- parameter prep ---------------------------------------------
__global__ void k_setup(const float* __restrict__ g1, const float* __restrict__ b1,
                        const float* __restrict__ m1, const float* __restrict__ v1,
                        const float* __restrict__ W1, const float* __restrict__ bias1,
                        const float* __restrict__ g2, const float* __restrict__ b2,
                        const float* __restrict__ m2, const float* __restrict__ v2) {
    int i = blockIdx.x * blockDim.x + threadIdx.x;
    if (i < DINF) {
        float s = g1[i] * rsqrtf(v1[i] + 1e-5f);
        g_A1[i] = s;
        g_B1[i] = b1[i] - m1[i] * s;
    }
    if (i < DH) {
        float s = g2[i] * rsqrtf(v2[i] + 1e-5f);
        g_A2[i] = s;
        g_B2[i] = (bias1[i] - m2[i]) * s + b2[i];
    }
    if (i < KTOT * DH) {
        int j = i / DH, o = i - j * DH;
        int hop = j / DPAD, d = j - hop * DPAD;
        float w = (d < DINF) ? W1[(hop * DH + o) * DINF + d] : 0.f;
        g_WcatH[o * KTOT + j] = __float2half_rn(w);   // transposed [o][j]
    }
}

// BN1 -> h0 (fp16), half2 stores; pad lanes 67..71 = 0
__global__ void k_bn1(const float* __restrict__ x) {
    int i = blockIdx.x * blockDim.x + threadIdx.x;
    if (i >= NN * NRU) return;
    int n = i / NRU, p = i - n * NRU;
    int d = 2 * p;
    float f0 = (d < DINF) ? x[n * DINF + d] * g_A1[d] + g_B1[d] : 0.f;
    float f1 = (d + 1 < DINF) ? x[n * DINF + d + 1] * g_A1[d + 1] + g_B1[d + 1] : 0.f;
    __half2 h = __floats2half2_rn(f0, f1);
    *reinterpret_cast<__half2*>(g_hbufH + (size_t)n * DPAD + d) = h;
}

// ---------------- gather hop (fp16, HFMA2) ------------------------------------
// dst[n] = sum_{in-edges} w * src[r]; 9 chunks of 16B; 4 rotating half2 acc sets
__device__ __forceinline__ void edge_acc(const char* sbase, int srcn, int wbits,
                                         int c, __half2* acc) {
    __half2 wh = *reinterpret_cast<__half2*>(&wbits);
    uint4 u = *reinterpret_cast<const uint4*>(sbase + (size_t)srcn * ROWB + c * 16);
    acc[0] = __hfma2(wh, *reinterpret_cast<__half2*>(&u.x), acc[0]);
    acc[1] = __hfma2(wh, *reinterpret_cast<__half2*>(&u.y), acc[1]);
    acc[2] = __hfma2(wh, *reinterpret_cast<__half2*>(&u.z), acc[2]);
    acc[3] = __hfma2(wh, *reinterpret_cast<__half2*>(&u.w), acc[3]);
}

__global__ void k_hop(const __half* __restrict__ src, __half* __restrict__ dst) {
    int idx = blockIdx.x * blockDim.x + threadIdx.x;
    if (idx >= NN * NG) return;
    int n = idx / NG, c = idx - n * NG;
    int s = g_off[n], e2 = g_off[n + 1];
    const char* sbase = reinterpret_cast<const char*>(src);

    __half2 zero = __floats2half2_rn(0.f, 0.f);
    __half2 A0[4] = {zero, zero, zero, zero};
    __half2 A1v[4] = {zero, zero, zero, zero};
    __half2 A2v[4] = {zero, zero, zero, zero};
    __half2 A3[4] = {zero, zero, zero, zero};

    int i = s;
    if ((i & 1) && i < e2) {             // peel to 16B-align csc index
        int2 pk = __ldg(&g_csc[i]);
        edge_acc(sbase, pk.x, pk.y, c, A0);
        i++;
    }
    int tog = 0;
    for (; i + 2 <= e2; i += 2, tog ^= 1) {
        int4 p = __ldg(reinterpret_cast<const int4*>(&g_csc[i]));   // 2 edges
        if (tog == 0) {
            edge_acc(sbase, p.x, p.y, c, A0);
            edge_acc(sbase, p.z, p.w, c, A1v);
        } else {
            edge_acc(sbase, p.x, p.y, c, A2v);
            edge_acc(sbase, p.z, p.w, c, A3);
        }
    }
    if (i < e2) {                         // tail edge
        int2 pk = __ldg(&g_csc[i]);
        edge_acc(sbase, pk.x, pk.y, c, A2v);
    }

    // combine: one fp16 pairwise level, then fp32
    uint4 ov;
    unsigned* ovp = reinterpret_cast<unsigned*>(&ov);
#pragma unroll
    for (int k = 0; k < 4; k++) {
        __half2 c0 = __hadd2(A0[k], A1v[k]);
        __half2 c1 = __hadd2(A2v[k], A3[k]);
        float2 f0 = __half22float2(c0);
        float2 f1 = __half22float2(c1);
        __half2 r = __floats2half2_rn(f0.x + f1.x, f0.y + f1.y);
        ovp[k] = *reinterpret_cast<unsigned*>(&r);
    }
    *reinterpret_cast<uint4*>(reinterpret_cast<char*>(dst) + (size_t)n * ROWB + c * 16) = ov;
}

// ---------------- fp16 tensor-core GEMM, cp.async 2-stage pipeline -----------
__device__ __forceinline__ void cp16(unsigned sdst, const void* gsrc, int sz) {
    asm volatile("cp.async.cg.shared.global [%0], [%1], 16, %2;"
                 :: "r"(sdst), "l"(gsrc), "r"(sz));
}

__global__ void __launch_bounds__(256) k_gemm(const float* __restrict__ W2) {
    __shared__ unsigned As[2][128][8];   // [stage][m][k-uint]
    __shared__ unsigned Bs[2][128][8];   // [stage][n][k-uint]
    __shared__ float W2s[4][128];
    __shared__ float A2s[128], B2s[128];
    __shared__ float ys[4][128];

    const int bm   = blockIdx.x * 128;
    const int tid  = threadIdx.x;
    const int lane = tid & 31;
    const int warp = tid >> 5;
    const int wm   = (warp & 1) * 64;
    const int wn   = (warp >> 1) * 32;
    const int gr   = lane >> 2;          // 0..7
    const int ct   = lane & 3;           // 0..3

    if (tid < 128) { A2s[tid] = g_A2[tid]; B2s[tid] = g_B2[tid]; }
#pragma unroll
    for (int l = 0; l < 2; l++) {
        int li = tid + l * 256;
        if (li < 512) {
            W2s[li >> 7][li & 127] = W2[li];
            ys[li >> 7][li & 127] = 0.f;
        }
    }

    float acc[4][4][4];
#pragma unroll
    for (int s = 0; s < 4; s++)
#pragma unroll
        for (int t = 0; t < 4; t++)
#pragma unroll
            for (int r = 0; r < 4; r++) acc[s][t][r] = 0.f;

    const uint4* hb4 = reinterpret_cast<const uint4*>(g_hbufH);
    const uint4* wc4 = reinterpret_cast<const uint4*>(g_WcatH);

    const int mro  = tid >> 1;
    const int gsel = tid & 1;
    const int an   = bm + mro;
    const int asz  = (an < NN) ? 16 : 0;
    const int anc  = (an < NN) ? an : 0;

    auto prefetch = [&](int st, int s) {
        int G = 2 * s + gsel;
        int hop = G / NG, off = G - hop * NG;
        unsigned ad = (unsigned)__cvta_generic_to_shared(&As[st][mro][gsel * 4]);
        cp16(ad, hb4 + (size_t)hop * (NN * NG) + (size_t)anc * NG + off, asz);
        unsigned bd = (unsigned)__cvta_generic_to_shared(&Bs[st][mro][gsel * 4]);
        cp16(bd, wc4 + (size_t)mro * NG * 4 + G, 16);
    };

    prefetch(0, 0);
    asm volatile("cp.async.commit_group;" ::: "memory");

    for (int s = 0; s < NSTEP; s++) {
        int st = s & 1;
        if (s + 1 < NSTEP) {
            prefetch(st ^ 1, s + 1);
            asm volatile("cp.async.commit_group;" ::: "memory");
            asm volatile("cp.async.wait_group 1;" ::: "memory");
        } else {
            asm volatile("cp.async.wait_group 0;" ::: "memory");
        }
        __syncthreads();

        unsigned bf[4][2];
#pragma unroll
        for (int t = 0; t < 4; t++) {
            int col = wn + t * 8 + gr;
            bf[t][0] = Bs[st][col][ct];
            bf[t][1] = Bs[st][col][ct + 4];
        }
#pragma unroll
        for (int si = 0; si < 4; si++) {
            int mrow = wm + si * 16 + gr;
            unsigned a0 = As[st][mrow][ct];
            unsigned a1 = As[st][mrow + 8][ct];
            unsigned a2 = As[st][mrow][ct + 4];
            unsigned a3 = As[st][mrow + 8][ct + 4];
#pragma unroll
            for (int t = 0; t < 4; t++) {
                asm volatile(
                    "mma.sync.aligned.m16n8k16.row.col.f32.f16.f16.f32 "
                    "{%0,%1,%2,%3}, {%4,%5,%6,%7}, {%8,%9}, {%0,%1,%2,%3};"
                    : "+f"(acc[si][t][0]), "+f"(acc[si][t][1]),
                      "+f"(acc[si][t][2]), "+f"(acc[si][t][3])
                    : "r"(a0), "r"(a1), "r"(a2), "r"(a3),
                      "r"(bf[t][0]), "r"(bf[t][1]));
            }
        }
        __syncthreads();
    }

    // epilogue: BN2+bias1+leaky, project onto W2 channels, smem-reduce
#pragma unroll
    for (int s = 0; s < 4; s++) {
#pragma unroll
        for (int rr = 0; rr < 2; rr++) {
            int m = wm + s * 16 + gr + rr * 8;
            float p0 = 0.f, p1 = 0.f, p2 = 0.f, p3 = 0.f;
#pragma unroll
            for (int t = 0; t < 4; t++) {
#pragma unroll
                for (int cc = 0; cc < 2; cc++) {
                    int o = wn + t * 8 + 2 * ct + cc;
                    int r = rr * 2 + cc;
                    float v = acc[s][t][r] * A2s[o] + B2s[o];
                    v = (v > 0.f) ? v : 0.01f * v;
                    p0 += v * W2s[0][o];
                    p1 += v * W2s[1][o];
                    p2 += v * W2s[2][o];
                    p3 += v * W2s[3][o];
                }
            }
            atomicAdd(&ys[0][m], p0);
            atomicAdd(&ys[1][m], p1);
            atomicAdd(&ys[2][m], p2);
            atomicAdd(&ys[3][m], p3);
        }
    }
    __syncthreads();
#pragma unroll
    for (int l = 0; l < 2; l++) {
        int li = tid + l * 256;
        int ch = li >> 7, m = li & 127;
        int n = bm + m;
        if (n < NN) g_y[ch][n] = ys[ch][m];
    }
}

// scalar gather hop: dst[n] = addin[n] (+bias) + sum w*src[r]
__global__ void k_shop(float* __restrict__ dst, const float* __restrict__ addin,
                       const float* __restrict__ src, const float* __restrict__ bias) {
    int n = blockIdx.x * blockDim.x + threadIdx.x;
    if (n >= NN) return;
    float acc = addin[n] + (bias ? bias[0] : 0.f);
    int e2 = g_off[n + 1];
#pragma unroll 4
    for (int i = g_off[n]; i < e2; i++) {
        int2 pk = __ldg(&g_csc[i]);
        float w = __half2float(__ushort_as_half((unsigned short)(pk.y & 0xFFFF)));
        acc += w * src[pk.x];
    }
    dst[n] = acc;
}

// ---------------- launch -----------------------------------------------------
extern "C" void kernel_launch(void* const* d_in, const int* in_sizes, int n_in,
                              void* d_out, int out_size) {
    const float* x     = (const float*)d_in[0];
    const int*   ei    = (const int*)  d_in[1];
    const float* g1    = (const float*)d_in[2];
    const float* b1    = (const float*)d_in[3];
    const float* m1    = (const float*)d_in[4];
    const float* v1    = (const float*)d_in[5];
    const float* W1    = (const float*)d_in[6];
    const float* bias1 = (const float*)d_in[7];
    const float* g2    = (const float*)d_in[8];
    const float* b2    = (const float*)d_in[9];
    const float* m2    = (const float*)d_in[10];
    const float* v2    = (const float*)d_in[11];
    const float* W2    = (const float*)d_in[12];
    const float* bias2 = (const float*)d_in[13];
    float* out = (float*)d_out;

    const int* row = ei;
    const int* col = ei + EE;

    const int T = 256;

    // CSC build
    k_zero<<<(NN + T - 1) / T, T>>>();
    k_deg<<<(EE + T - 1) / T, T>>>(col);
    k_scanA<<<NBLK, SCAN_B>>>();
    k_scanC<<<NBLK, SCAN_B>>>();
    k_fill<<<(EE + T - 1) / T, T>>>(row, col);

    k_setup<<<(KTOT * DH + T - 1) / T, T>>>(g1, b1, m1, v1, W1, bias1, g2, b2, m2, v2);
    k_bn1<<<(NN * NRU + T - 1) / T, T>>>(x);

    // layer-1 propagation: 3 gather hops at fp16 width 72
    {
        __half* h0;
        cudaGetSymbolAddress((void**)&h0, g_hbufH);
        __half* h1 = h0 + (size_t)NN * DPAD;
        __half* h2 = h1 + (size_t)NN * DPAD;
        __half* h3 = h2 + (size_t)NN * DPAD;
        int blocks = (NN * NG + T - 1) / T;
        k_hop<<<blocks, T>>>(h0, h1);
        k_hop<<<blocks, T>>>(h1, h2);
        k_hop<<<blocks, T>>>(h2, h3);
    }

    // fused fp16 GEMM + BN2 + leaky + W2 projection (produces g_y directly)
    k_gemm<<<(NN + 127) / 128, 256>>>(W2);

    // Horner on scalar channels: out = y0 + A(y1 + A(y2 + A y3)) + bias2
    {
        float* ta; float* tb; float* y0;
        cudaGetSymbolAddress((void**)&ta, g_ta);
        cudaGetSymbolAddress((void**)&tb, g_tb);
        cudaGetSymbolAddress((void**)&y0, g_y);
        float* y1 = y0 + NN; float* y2 = y1 + NN; float* y3 = y2 + NN;
        int bn = (NN + T - 1) / T;
        k_shop<<<bn, T>>>(tb, y2, y3, nullptr);
        k_shop<<<bn, T>>>(ta, y1, tb, nullptr);
        k_shop<<<bn, T>>>(out, y0, ta, bias2);
    }
    (void)in_sizes; (void)n_in; (void)out_size;
}

// round 10
// speedup vs baseline: 2.9844x; 1.0385x over previous
#include <cuda_runtime.h>
#include <cuda_fp16.h>

#define NN   100000
#define EE   1600000
#define DINF 67
#define DPAD 72          // padded feature width in halves (9 x uint4)
#define ROWB 144         // bytes per hop-row
#define NRU  36          // half2 pairs per hop-row
#define NG   9           // uint4 groups per hop-row
#define DH   128
#define KTOT 288         // 4 * DPAD halves
#define NSTEP 18         // GEMM k-steps (8 uints each)
#define SCAN_B 1024
#define NBLK   98        // ceil(100000/1024)

// ---------------- scratch (static device memory; no allocs allowed) ----------
__device__ __align__(16) __half g_hbufH[4 * NN * DPAD]; // h0..h3 (GEMM input)
__device__ __align__(16) __half g_ubufH[3 * NN * DPAD]; // u0..u2 (hop source)
__device__ int    g_degi[NN];
__device__ float  g_dis[NN];
__device__ int    g_off[NN + 1];            // CSC offsets
__device__ int    g_cursor[NN];
__device__ int    g_blocksum[NBLK + 1];
__device__ __align__(16) int g_csci[EE];    // CSC source indices (weightless)
__device__ __align__(16) __half g_WcatH[DH * KTOT];  // W1 transposed [o][j]
__device__ float  g_A1[DINF], g_B1[DINF];   // BN1 folded affine
__device__ float  g_A2[DH],   g_B2[DH];     // BN2 + bias1 folded affine
__device__ float  g_y[4][NN];               // layer2 channels (1..3 pre-scaled)
__device__ float  g_ta[NN], g_tb[NN];       // scalar propagation buffers

// ---------------- CSC build ---------------------------------------------------
__global__ void k_zero() {
    int i = blockIdx.x * blockDim.x + threadIdx.x;
    if (i < NN) g_degi[i] = 0;
}

__global__ void k_deg(const int* __restrict__ col) {
    int e = blockIdx.x * blockDim.x + threadIdx.x;
    if (e < EE) atomicAdd(&g_degi[col[e]], 1);
}

__global__ void k_scanA() {
    __shared__ int s[SCAN_B];
    int g = blockIdx.x * SCAN_B + threadIdx.x;
    int v = (g < NN) ? g_degi[g] : 0;
    s[threadIdx.x] = v;
    __syncthreads();
#pragma unroll
    for (int d = 1; d < SCAN_B; d <<= 1) {
        int t = (threadIdx.x >= d) ? s[threadIdx.x - d] : 0;
        __syncthreads();
        s[threadIdx.x] += t;
        __syncthreads();
    }
    if (g < NN) g_off[g] = s[threadIdx.x] - v;
    if (threadIdx.x == SCAN_B - 1) g_blocksum[blockIdx.x] = s[SCAN_B - 1];
}

// merged: every block scans the 98 block sums itself, then finalizes its slice
__global__ void k_scanC() {
    __shared__ int s[128];
    int tix = threadIdx.x;
    if (tix < 128) s[tix] = (tix < NBLK) ? g_blocksum[tix] : 0;
    __syncthreads();
#pragma unroll
    for (int d = 1; d < 128; d <<= 1) {
        int t = (tix >= d && tix < 128) ? s[tix - d] : 0;
        __syncthreads();
        if (tix < 128) s[tix] += t;
        __syncthreads();
    }
    int pref = (blockIdx.x == 0) ? 0 : s[blockIdx.x - 1];
    int g = blockIdx.x * SCAN_B + tix;
    if (g < NN) {
        int o = g_off[g] + pref;
        g_off[g] = o;
        g_cursor[g] = o;
        int dg = g_degi[g];
        g_dis[g] = (dg > 0) ? rsqrtf((float)dg) : 0.f;
    }
    if (g == 0) g_off[NN] = EE;
}

// weightless fill: just place the source index
__global__ void k_fill(const int* __restrict__ row, const int* __restrict__ col) {
    int e = blockIdx.x * blockDim.x + threadIdx.x;
    if (e < EE) {
        int p = atomicAdd(&g_cursor[col[e]], 1);
        g_csci[p] = row[e];
    }
}

// ---------------- parameter prep ---------------------------------------------
__global__ void k_setup(const float* __restrict__ g1, const float* __restrict__ b1,
                        const float* __restrict__ m1, const float* __restrict__ v1,
                        const float* __restrict__ W1, const float* __restrict__ bias1,
                        const float* __restrict__ g2, const float* __restrict__ b2,
                        const float* __restrict__ m2, const float* __restrict__ v2) {
    int i = blockIdx.x * blockDim.x + threadIdx.x;
    if (i < DINF) {
        float s = g1[i] * rsqrtf(v1[i] + 1e-5f);
        g_A1[i] = s;
        g_B1[i] = b1[i] - m1[i] * s;
    }
    if (i < DH) {
        float s = g2[i] * rsqrtf(v2[i] + 1e-5f);
        g_A2[i] = s;
        g_B2[i] = (bias1[i] - m2[i]) * s + b2[i];
    }
    if (i < KTOT * DH) {
        int j = i / DH, o = i - j * DH;
        int hop = j / DPAD, d = j - hop * DPAD;
        float w = (d < DINF) ? W1[(hop * DH + o) * DINF + d] : 0.f;
        g_WcatH[o * KTOT + j] = __float2half_rn(w);   // transposed [o][j]
    }
}

// BN1 -> h0 (raw) and u0 = dis*h0 (scaled hop source)
__global__ void k_bn1(const float* __restrict__ x) {
    int i = blockIdx.x * blockDim.x + threadIdx.x;
    if (i >= NN * NRU) return;
    int n = i / NRU, p = i - n * NRU;
    int d = 2 * p;
    float f0 = (d < DINF) ? x[n * DINF + d] * g_A1[d] + g_B1[d] : 0.f;
    float f1 = (d + 1 < DINF) ? x[n * DINF + d + 1] * g_A1[d + 1] + g_B1[d + 1] : 0.f;
    float dis = g_dis[n];
    *reinterpret_cast<__half2*>(g_hbufH + (size_t)n * DPAD + d) =
        __floats2half2_rn(f0, f1);
    *reinterpret_cast<__half2*>(g_ubufH + (size_t)n * DPAD + d) =
        __floats2half2_rn(f0 * dis, f1 * dis);
}

// ---------------- gather hop (weightless HADD2) -------------------------------
// S[c] = sum_{r in N(c)} u_src[r];  h_out = dis*S;  u_out = dis^2*S
__device__ __forceinline__ void edge_add(const char* sbase, int srcn, int c,
                                         __half2* acc) {
    uint4 u = *reinterpret_cast<const uint4*>(sbase + (size_t)srcn * ROWB + c * 16);
    acc[0] = __hadd2(acc[0], *reinterpret_cast<__half2*>(&u.x));
    acc[1] = __hadd2(acc[1], *reinterpret_cast<__half2*>(&u.y));
    acc[2] = __hadd2(acc[2], *reinterpret_cast<__half2*>(&u.z));
    acc[3] = __hadd2(acc[3], *reinterpret_cast<__half2*>(&u.w));
}

__global__ void k_hop(const __half* __restrict__ srcU, __half* __restrict__ dstH,
                      __half* __restrict__ dstU, int writeU) {
    int idx = blockIdx.x * blockDim.x + threadIdx.x;
    if (idx >= NN * NG) return;
    int n = idx / NG, c = idx - n * NG;
    int s = g_off[n], e2 = g_off[n + 1];
    const char* sbase = reinterpret_cast<const char*>(srcU);

    __half2 zero = __floats2half2_rn(0.f, 0.f);
    __half2 A[4][4];
#pragma unroll
    for (int a = 0; a < 4; a++)
#pragma unroll
        for (int k = 0; k < 4; k++) A[a][k] = zero;

    int i = s;
    while (i < e2 && (i & 3)) {                 // peel to 16B-align csci index
        edge_add(sbase, __ldg(&g_csci[i]), c, A[i & 3]);
        i++;
    }
    for (; i + 4 <= e2; i += 4) {               // 4 edges per int4
        int4 p = __ldg(reinterpret_cast<const int4*>(&g_csci[i]));
        edge_add(sbase, p.x, c, A[0]);
        edge_add(sbase, p.y, c, A[1]);
        edge_add(sbase, p.z, c, A[2]);
        edge_add(sbase, p.w, c, A[3]);
    }
    for (; i < e2; i++)                          // tail
        edge_add(sbase, __ldg(&g_csci[i]), c, A[i & 3]);

    float dis = g_dis[n];
    float d2  = dis * dis;
    uint4 hv, uv;
    unsigned* hp = reinterpret_cast<unsigned*>(&hv);
    unsigned* up = reinterpret_cast<unsigned*>(&uv);
#pragma unroll
    for (int k = 0; k < 4; k++) {
        __half2 c0 = __hadd2(A[0][k], A[1][k]);
        __half2 c1 = __hadd2(A[2][k], A[3][k]);
        float2 f0 = __half22float2(c0);
        float2 f1 = __half22float2(c1);
        float sx = f0.x + f1.x, sy = f0.y + f1.y;
        __half2 h = __floats2half2_rn(sx * dis, sy * dis);
        __half2 u = __floats2half2_rn(sx * d2,  sy * d2);
        hp[k] = *reinterpret_cast<unsigned*>(&h);
        up[k] = *reinterpret_cast<unsigned*>(&u);
    }
    char* hdst = reinterpret_cast<char*>(dstH) + (size_t)n * ROWB + c * 16;
    *reinterpret_cast<uint4*>(hdst) = hv;
    if (writeU) {
        char* udst = reinterpret_cast<char*>(dstU) + (size_t)n * ROWB + c * 16;
        *reinterpret_cast<uint4*>(udst) = uv;
    }
}

// ---------------- fp16 tensor-core GEMM, cp.async 2-stage pipeline -----------
__device__ __forceinline__ void cp16(unsigned sdst, const void* gsrc, int sz) {
    asm volatile("cp.async.cg.shared.global [%0], [%1], 16, %2;"
                 :: "r"(sdst), "l"(gsrc), "r"(sz));
}

__global__ void __launch_bounds__(256) k_gemm(const float* __restrict__ W2) {
    __shared__ unsigned As[2][128][8];   // [stage][m][k-uint]
    __shared__ unsigned Bs[2][128][8];   // [stage][n][k-uint]
    __shared__ float W2s[4][128];
    __shared__ float A2s[128], B2s[128];
    __shared__ float ys[4][128];

    const int bm   = blockIdx.x * 128;
    const int tid  = threadIdx.x;
    const int lane = tid & 31;
    const int warp = tid >> 5;
    const int wm   = (warp & 1) * 64;
    const int wn   = (warp >> 1) * 32;
    const int gr   = lane >> 2;          // 0..7
    const int ct   = lane & 3;           // 0..3

    if (tid < 128) { A2s[tid] = g_A2[tid]; B2s[tid] = g_B2[tid]; }
#pragma unroll
    for (int l = 0; l < 2; l++) {
        int li = tid + l * 256;
        if (li < 512) {
            W2s[li >> 7][li & 127] = W2[li];
            ys[li >> 7][li & 127] = 0.f;
        }
    }

    float acc[4][4][4];
#pragma unroll
    for (int s = 0; s < 4; s++)
#pragma unroll
        for (int t = 0; t < 4; t++)
#pragma unroll
            for (int r = 0; r < 4; r++) acc[s][t][r] = 0.f;

    const uint4* hb4 = reinterpret_cast<const uint4*>(g_hbufH);
    const uint4* wc4 = reinterpret_cast<const uint4*>(g_WcatH);

    const int mro  = tid >> 1;
    const int gsel = tid & 1;
    const int an   = bm + mro;
    const int asz  = (an < NN) ? 16 : 0;
    const int anc  = (an < NN) ? an : 0;

    auto prefetch = [&](int st, int s) {
        int G = 2 * s + gsel;
        int hop = G / NG, off = G - hop * NG;
        unsigned ad = (unsigned)__cvta_generic_to_shared(&As[st][mro][gsel * 4]);
        cp16(ad, hb4 + (size_t)hop * (NN * NG) + (size_t)anc * NG + off, asz);
        unsigned bd = (unsigned)__cvta_generic_to_shared(&Bs[st][mro][gsel * 4]);
        cp16(bd, wc4 + (size_t)mro * NG * 4 + G, 16);
    };

    prefetch(0, 0);
    asm volatile("cp.async.commit_group;" ::: "memory");

    for (int s = 0; s < NSTEP; s++) {
        int st = s & 1;
        if (s + 1 < NSTEP) {
            prefetch(st ^ 1, s + 1);
            asm volatile("cp.async.commit_group;" ::: "memory");
            asm volatile("cp.async.wait_group 1;" ::: "memory");
        } else {
            asm volatile("cp.async.wait_group 0;" ::: "memory");
        }
        __syncthreads();

        unsigned bf[4][2];
#pragma unroll
        for (int t = 0; t < 4; t++) {
            int col = wn + t * 8 + gr;
            bf[t][0] = Bs[st][col][ct];
            bf[t][1] = Bs[st][col][ct + 4];
        }
#pragma unroll
        for (int si = 0; si < 4; si++) {
            int mrow = wm + si * 16 + gr;
            unsigned a0 = As[st][mrow][ct];
            unsigned a1 = As[st][mrow + 8][ct];
            unsigned a2 = As[st][mrow][ct + 4];
            unsigned a3 = As[st][mrow + 8][ct + 4];
#pragma unroll
            for (int t = 0; t < 4; t++) {
                asm volatile(
                    "mma.sync.aligned.m16n8k16.row.col.f32.f16.f16.f32 "
                    "{%0,%1,%2,%3}, {%4,%5,%6,%7}, {%8,%9}, {%0,%1,%2,%3};"
                    : "+f"(acc[si][t][0]), "+f"(acc[si][t][1]),
                      "+f"(acc[si][t][2]), "+f"(acc[si][t][3])
                    : "r"(a0), "r"(a1), "r"(a2), "r"(a3),
                      "r"(bf[t][0]), "r"(bf[t][1]));
            }
        }
        __syncthreads();
    }

    // epilogue: BN2+bias1+leaky, project onto W2 channels, smem-reduce
#pragma unroll
    for (int s = 0; s < 4; s++) {
#pragma unroll
        for (int rr = 0; rr < 2; rr++) {
            int m = wm + s * 16 + gr + rr * 8;
            float p0 = 0.f, p1 = 0.f, p2 = 0.f, p3 = 0.f;
#pragma unroll
            for (int t = 0; t < 4; t++) {
#pragma unroll
                for (int cc = 0; cc < 2; cc++) {
                    int o = wn + t * 8 + 2 * ct + cc;
                    int r = rr * 2 + cc;
                    float v = acc[s][t][r] * A2s[o] + B2s[o];
                    v = (v > 0.f) ? v : 0.01f * v;
                    p0 += v * W2s[0][o];
                    p1 += v * W2s[1][o];
                    p2 += v * W2s[2][o];
                    p3 += v * W2s[3][o];
                }
            }
            atomicAdd(&ys[0][m], p0);
            atomicAdd(&ys[1][m], p1);
            atomicAdd(&ys[2][m], p2);
            atomicAdd(&ys[3][m], p3);
        }
    }
    __syncthreads();
    // channels 1..3 pre-scaled by dis[n] for the weightless scalar Horner
#pragma unroll
    for (int l = 0; l < 2; l++) {
        int li = tid + l * 256;
        int ch = li >> 7, m = li & 127;
        int n = bm + m;
        if (n < NN) {
            float sc = (ch == 0) ? 1.f : g_dis[n];
            g_y[ch][n] = ys[ch][m] * sc;
        }
    }
}

// weightless scalar gather: dst[n] = addin[n] (+bias) + scale(n)*sum src[r]
// sq=1: scale=dis^2 (stay in scaled domain); sq=0: scale=dis (final output)
__global__ void k_shop(float* __restrict__ dst, const float* __restrict__ addin,
                       const float* __restrict__ src, const float* __restrict__ bias,
                       int sq) {
    int n = blockIdx.x * blockDim.x + threadIdx.x;
    if (n >= NN) return;
    float acc = 0.f;
    int e2 = g_off[n + 1];
#pragma unroll 4
    for (int i = g_off[n]; i < e2; i++)
        acc += src[__ldg(&g_csci[i])];
    float dis = g_dis[n];
    float sc = sq ? dis * dis : dis;
    dst[n] = addin[n] + (bias ? bias[0] : 0.f) + sc * acc;
}

// ---------------- launch -----------------------------------------------------
extern "C" void kernel_launch(void* const* d_in, const int* in_sizes, int n_in,
                              void* d_out, int out_size) {
    const float* x     = (const float*)d_in[0];
    const int*   ei    = (const int*)  d_in[1];
    const float* g1    = (const float*)d_in[2];
    const float* b1    = (const float*)d_in[3];
    const float* m1    = (const float*)d_in[4];
    const float* v1    = (const float*)d_in[5];
    const float* W1    = (const float*)d_in[6];
    const float* bias1 = (const float*)d_in[7];
    const float* g2    = (const float*)d_in[8];
    const float* b2    = (const float*)d_in[9];
    const float* m2    = (const float*)d_in[10];
    const float* v2    = (const float*)d_in[11];
    const float* W2    = (const float*)d_in[12];
    const float* bias2 = (const float*)d_in[13];
    float* out = (float*)d_out;

    const int* row = ei;
    const int* col = ei + EE;

    const int T = 256;

    // CSC build (weightless)
    k_zero<<<(NN + T - 1) / T, T>>>();
    k_deg<<<(EE + T - 1) / T, T>>>(col);
    k_scanA<<<NBLK, SCAN_B>>>();
    k_scanC<<<NBLK, SCAN_B>>>();
    k_fill<<<(EE + T - 1) / T, T>>>(row, col);

    k_setup<<<(KTOT * DH + T - 1) / T, T>>>(g1, b1, m1, v1, W1, bias1, g2, b2, m2, v2);
    k_bn1<<<(NN * NRU + T - 1) / T, T>>>(x);   // needs g_dis -> after scanC

    // layer-1 propagation: 3 weightless gather hops (scaled domain)
    {
        __half* h0; __half* u0;
        cudaGetSymbolAddress((void**)&h0, g_hbufH);
        cudaGetSymbolAddress((void**)&u0, g_ubufH);
        __half* h1 = h0 + (size_t)NN * DPAD;
        __half* h2 = h1 + (size_t)NN * DPAD;
        __half* h3 = h2 + (size_t)NN * DPAD;
        __half* u1 = u0 + (size_t)NN * DPAD;
        __half* u2 = u1 + (size_t)NN * DPAD;
        int blocks = (NN * NG + T - 1) / T;
        k_hop<<<blocks, T>>>(u0, h1, u1, 1);
        k_hop<<<blocks, T>>>(u1, h2, u2, 1);
        k_hop<<<blocks, T>>>(u2, h3, u2, 0);   // u3 not needed
    }

    // fused fp16 GEMM + BN2 + leaky + W2 projection (g_y, ch1..3 dis-scaled)
    k_gemm<<<(NN + 127) / 128, 256>>>(W2);

    // weightless Horner: out = y0 + A(y1 + A(y2 + A y3)) + bias2
    {
        float* ta; float* tb; float* y0;
        cudaGetSymbolAddress((void**)&ta, g_ta);
        cudaGetSymbolAddress((void**)&tb, g_tb);
        cudaGetSymbolAddress((void**)&y0, g_y);
        float* y1 = y0 + NN; float* y2 = y1 + NN; float* y3 = y2 + NN;
        int bn = (NN + T - 1) / T;
        k_shop<<<bn, T>>>(tb, y2, y3, nullptr, 1);   // t1^ = y2^ + dis^2*sum y3^
        k_shop<<<bn, T>>>(ta, y1, tb, nullptr, 1);   // t2^ = y1^ + dis^2*sum t1^
        k_shop<<<bn, T>>>(out, y0, ta, bias2, 0);    // out = y0 + dis*sum t2^ + b
    }
    (void)in_sizes; (void)n_in; (void)out_size;
}

// round 11
// speedup vs baseline: 3.0370x; 1.0176x over previous
#include <cuda_runtime.h>
#include <cuda_fp16.h>

#define NN   100000
#define EE   1600000
#define DINF 67
#define DPAD 72          // padded feature width in halves (9 x uint4)
#define ROWB 144         // bytes per hop-row
#define NRU  36          // half2 pairs per hop-row
#define NG   9           // uint4 groups per hop-row
#define DH   128
#define KTOT 288         // 4 * DPAD halves
#define NSTEP 18         // GEMM k-steps (8 uints each)
#define SCAN_B 1024
#define NBLK   98        // ceil(100000/1024)
#define FB    6250       // fill blocks (EE/256)
#define BB    14063      // bn1 blocks ((NN*NRU+255)/256)

// ---------------- scratch (static device memory; no allocs allowed) ----------
__device__ __align__(16) __half g_hbufH[4 * NN * DPAD]; // h0..h3 (GEMM input)
__device__ __align__(16) __half g_ubufH[3 * NN * DPAD]; // u0..u2 (hop source)
__device__ int    g_degi[NN];
__device__ float  g_dis[NN];
__device__ int    g_off[NN + 1];            // CSC offsets
__device__ int    g_cursor[NN];
__device__ int    g_blocksum[NBLK + 1];
__device__ __align__(16) int g_csci[EE];    // CSC source indices (weightless)
__device__ __align__(16) __half g_WcatH[DH * KTOT];  // W1 transposed [o][j]
__device__ float  g_A1[DINF], g_B1[DINF];   // BN1 folded affine
__device__ float  g_A2[DH],   g_B2[DH];     // BN2 + bias1 folded affine
__device__ float  g_y[4][NN];               // layer2 channels (1..3 pre-scaled)
__device__ float  g_ta[NN], g_tb[NN];       // scalar propagation buffers

// ---------------- init: zero deg + all parameter prep (merged) ----------------
__global__ void k_init(const float* __restrict__ g1, const float* __restrict__ b1,
                       const float* __restrict__ m1, const float* __restrict__ v1,
                       const float* __restrict__ W1, const float* __restrict__ bias1,
                       const float* __restrict__ g2, const float* __restrict__ b2,
                       const float* __restrict__ m2, const float* __restrict__ v2) {
    int i = blockIdx.x * blockDim.x + threadIdx.x;
    if (i < NN) g_degi[i] = 0;
    if (i < DINF) {
        float s = g1[i] * rsqrtf(v1[i] + 1e-5f);
        g_A1[i] = s;
        g_B1[i] = b1[i] - m1[i] * s;
    }
    if (i < DH) {
        float s = g2[i] * rsqrtf(v2[i] + 1e-5f);
        g_A2[i] = s;
        g_B2[i] = (bias1[i] - m2[i]) * s + b2[i];
    }
    if (i < KTOT * DH) {
        int j = i / DH, o = i - j * DH;
        int hop = j / DPAD, d = j - hop * DPAD;
        float w = (d < DINF) ? W1[(hop * DH + o) * DINF + d] : 0.f;
        g_WcatH[o * KTOT + j] = __float2half_rn(w);   // transposed [o][j]
    }
}

__global__ void k_deg(const int* __restrict__ col) {
    int e = blockIdx.x * blockDim.x + threadIdx.x;
    if (e < EE) atomicAdd(&g_degi[col[e]], 1);
}

// shfl-based block scan: exclusive offsets (block-local) + block totals
__global__ void k_scanA() {
    __shared__ int ws[32];
    int g = blockIdx.x * SCAN_B + threadIdx.x;
    int lane = threadIdx.x & 31, wid = threadIdx.x >> 5;
    int v = (g < NN) ? g_degi[g] : 0;
    int x = v;
#pragma unroll
    for (int d = 1; d < 32; d <<= 1) {
        int t = __shfl_up_sync(0xFFFFFFFFu, x, d);
        if (lane >= d) x += t;
    }
    if (lane == 31) ws[wid] = x;
    __syncthreads();
    if (wid == 0) {
        int y = ws[lane];
#pragma unroll
        for (int d = 1; d < 32; d <<= 1) {
            int t = __shfl_up_sync(0xFFFFFFFFu, y, d);
            if (lane >= d) y += t;
        }
        ws[lane] = y;
    }
    __syncthreads();
    int incl = x + ((wid > 0) ? ws[wid - 1] : 0);
    if (g < NN) g_off[g] = incl - v;           // exclusive within block
    if (threadIdx.x == SCAN_B - 1) g_blocksum[blockIdx.x] = incl;
}

// merged: every block scans the 98 block sums itself, then finalizes its slice
__global__ void k_scanC() {
    __shared__ int s[128];
    int tix = threadIdx.x;
    if (tix < 128) s[tix] = (tix < NBLK) ? g_blocksum[tix] : 0;
    __syncthreads();
#pragma unroll
    for (int d = 1; d < 128; d <<= 1) {
        int t = (tix >= d && tix < 128) ? s[tix - d] : 0;
        __syncthreads();
        if (tix < 128) s[tix] += t;
        __syncthreads();
    }
    int pref = (blockIdx.x == 0) ? 0 : s[blockIdx.x - 1];
    int g = blockIdx.x * SCAN_B + tix;
    if (g < NN) {
        int o = g_off[g] + pref;
        g_off[g] = o;
        g_cursor[g] = o;
        int dg = g_degi[g];
        g_dis[g] = (dg > 0) ? rsqrtf((float)dg) : 0.f;
    }
    if (g == 0) g_off[NN] = EE;
}

// merged fill + bn1 (independent, both require scanC): partitioned by blockIdx
__global__ void k_fillbn1(const int* __restrict__ row, const int* __restrict__ col,
                          const float* __restrict__ x) {
    if (blockIdx.x < FB) {
        int e = blockIdx.x * blockDim.x + threadIdx.x;
        if (e < EE) {
            int p = atomicAdd(&g_cursor[col[e]], 1);
            g_csci[p] = row[e];
        }
    } else {
        int i = (blockIdx.x - FB) * blockDim.x + threadIdx.x;
        if (i >= NN * NRU) return;
        int n = i / NRU, p = i - n * NRU;
        int d = 2 * p;
        float f0 = (d < DINF) ? x[n * DINF + d] * g_A1[d] + g_B1[d] : 0.f;
        float f1 = (d + 1 < DINF) ? x[n * DINF + d + 1] * g_A1[d + 1] + g_B1[d + 1] : 0.f;
        float dis = g_dis[n];
        *reinterpret_cast<__half2*>(g_hbufH + (size_t)n * DPAD + d) =
            __floats2half2_rn(f0, f1);
        *reinterpret_cast<__half2*>(g_ubufH + (size_t)n * DPAD + d) =
            __floats2half2_rn(f0 * dis, f1 * dis);
    }
}

// ---------------- gather hop (weightless HADD2) -------------------------------
// S[c] = sum_{r in N(c)} u_src[r];  h_out = dis*S;  u_out = dis^2*S
__device__ __forceinline__ void edge_add(const char* sbase, int srcn, int c,
                                         __half2* acc) {
    uint4 u = *reinterpret_cast<const uint4*>(sbase + (size_t)srcn * ROWB + c * 16);
    acc[0] = __hadd2(acc[0], *reinterpret_cast<__half2*>(&u.x));
    acc[1] = __hadd2(acc[1], *reinterpret_cast<__half2*>(&u.y));
    acc[2] = __hadd2(acc[2], *reinterpret_cast<__half2*>(&u.z));
    acc[3] = __hadd2(acc[3], *reinterpret_cast<__half2*>(&u.w));
}

__global__ void k_hop(const __half* __restrict__ srcU, __half* __restrict__ dstH,
                      __half* __restrict__ dstU, int writeU) {
    int idx = blockIdx.x * blockDim.x + threadIdx.x;
    if (idx >= NN * NG) return;
    int n = idx / NG, c = idx - n * NG;
    int s = g_off[n], e2 = g_off[n + 1];
    const char* sbase = reinterpret_cast<const char*>(srcU);

    __half2 zero = __floats2half2_rn(0.f, 0.f);
    __half2 A[4][4];
#pragma unroll
    for (int a = 0; a < 4; a++)
#pragma unroll
        for (int k = 0; k < 4; k++) A[a][k] = zero;

    int i = s;
    while (i < e2 && (i & 3)) {                 // peel to 16B-align csci index
        edge_add(sbase, __ldg(&g_csci[i]), c, A[i & 3]);
        i++;
    }
    for (; i + 4 <= e2; i += 4) {               // 4 edges per int4
        int4 p = __ldg(reinterpret_cast<const int4*>(&g_csci[i]));
        edge_add(sbase, p.x, c, A[0]);
        edge_add(sbase, p.y, c, A[1]);
        edge_add(sbase, p.z, c, A[2]);
        edge_add(sbase, p.w, c, A[3]);
    }
    for (; i < e2; i++)                          // tail
        edge_add(sbase, __ldg(&g_csci[i]), c, A[i & 3]);

    float dis = g_dis[n];
    float d2  = dis * dis;
    uint4 hv, uv;
    unsigned* hp = reinterpret_cast<unsigned*>(&hv);
    unsigned* up = reinterpret_cast<unsigned*>(&uv);
#pragma unroll
    for (int k = 0; k < 4; k++) {
        __half2 c0 = __hadd2(A[0][k], A[1][k]);
        __half2 c1 = __hadd2(A[2][k], A[3][k]);
        float2 f0 = __half22float2(c0);
        float2 f1 = __half22float2(c1);
        float sx = f0.x + f1.x, sy = f0.y + f1.y;
        __half2 h = __floats2half2_rn(sx * dis, sy * dis);
        __half2 u = __floats2half2_rn(sx * d2,  sy * d2);
        hp[k] = *reinterpret_cast<unsigned*>(&h);
        up[k] = *reinterpret_cast<unsigned*>(&u);
    }
    char* hdst = reinterpret_cast<char*>(dstH) + (size_t)n * ROWB + c * 16;
    *reinterpret_cast<uint4*>(hdst) = hv;
    if (writeU) {
        char* udst = reinterpret_cast<char*>(dstU) + (size_t)n * ROWB + c * 16;
        *reinterpret_cast<uint4*>(udst) = uv;
    }
}

// ---------------- fp16 tensor-core GEMM, cp.async 2-stage pipeline -----------
__device__ __forceinline__ void cp16(unsigned sdst, const void* gsrc, int sz) {
    asm volatile("cp.async.cg.shared.global [%0], [%1], 16, %2;"
                 :: "r"(sdst), "l"(gsrc), "r"(sz));
}

__global__ void __launch_bounds__(256) k_gemm(const float* __restrict__ W2) {
    __shared__ unsigned As[2][128][8];   // [stage][m][k-uint]
    __shared__ unsigned Bs[2][128][8];   // [stage][n][k-uint]
    __shared__ float W2s[4][128];
    __shared__ float A2s[128], B2s[128];
    __shared__ float ys[4][128];

    const int bm   = blockIdx.x * 128;
    const int tid  = threadIdx.x;
    const int lane = tid & 31;
    const int warp = tid >> 5;
    const int wm   = (warp & 1) * 64;
    const int wn   = (warp >> 1) * 32;
    const int gr   = lane >> 2;          // 0..7
    const int ct   = lane & 3;           // 0..3

    if (tid < 128) { A2s[tid] = g_A2[tid]; B2s[tid] = g_B2[tid]; }
#pragma unroll
    for (int l = 0; l < 2; l++) {
        int li = tid + l * 256;
        if (li < 512) {
            W2s[li >> 7][li & 127] = W2[li];
            ys[li >> 7][li & 127] = 0.f;
        }
    }

    float acc[4][4][4];
#pragma unroll
    for (int s = 0; s < 4; s++)
#pragma unroll
        for (int t = 0; t < 4; t++)
#pragma unroll
            for (int r = 0; r < 4; r++) acc[s][t][r] = 0.f;

    const uint4* hb4 = reinterpret_cast<const uint4*>(g_hbufH);
    const uint4* wc4 = reinterpret_cast<const uint4*>(g_WcatH);

    const int mro  = tid >> 1;
    const int gsel = tid & 1;
    const int an   = bm + mro;
    const int asz  = (an < NN) ? 16 : 0;
    const int anc  = (an < NN) ? an : 0;

    auto prefetch = [&](int st, int s) {
        int G = 2 * s + gsel;
        int hop = G / NG, off = G - hop * NG;
        unsigned ad = (unsigned)__cvta_generic_to_shared(&As[st][mro][gsel * 4]);
        cp16(ad, hb4 + (size_t)hop * (NN * NG) + (size_t)anc * NG + off, asz);
        unsigned bd = (unsigned)__cvta_generic_to_shared(&Bs[st][mro][gsel * 4]);
        cp16(bd, wc4 + (size_t)mro * NG * 4 + G, 16);
    };

    prefetch(0, 0);
    asm volatile("cp.async.commit_group;" ::: "memory");

    for (int s = 0; s < NSTEP; s++) {
        int st = s & 1;
        if (s + 1 < NSTEP) {
            prefetch(st ^ 1, s + 1);
            asm volatile("cp.async.commit_group;" ::: "memory");
            asm volatile("cp.async.wait_group 1;" ::: "memory");
        } else {
            asm volatile("cp.async.wait_group 0;" ::: "memory");
        }
        __syncthreads();

        unsigned bf[4][2];
#pragma unroll
        for (int t = 0; t < 4; t++) {
            int col = wn + t * 8 + gr;
            bf[t][0] = Bs[st][col][ct];
            bf[t][1] = Bs[st][col][ct + 4];
        }
#pragma unroll
        for (int si = 0; si < 4; si++) {
            int mrow = wm + si * 16 + gr;
            unsigned a0 = As[st][mrow][ct];
            unsigned a1 = As[st][mrow + 8][ct];
            unsigned a2 = As[st][mrow][ct + 4];
            unsigned a3 = As[st][mrow + 8][ct + 4];
#pragma unroll
            for (int t = 0; t < 4; t++) {
                asm volatile(
                    "mma.sync.aligned.m16n8k16.row.col.f32.f16.f16.f32 "
                    "{%0,%1,%2,%3}, {%4,%5,%6,%7}, {%8,%9}, {%0,%1,%2,%3};"
                    : "+f"(acc[si][t][0]), "+f"(acc[si][t][1]),
                      "+f"(acc[si][t][2]), "+f"(acc[si][t][3])
                    : "r"(a0), "r"(a1), "r"(a2), "r"(a3),
                      "r"(bf[t][0]), "r"(bf[t][1]));
            }
        }
        __syncthreads();
    }

    // epilogue: BN2+bias1+leaky, project onto W2 channels, smem-reduce
#pragma unroll
    for (int s = 0; s < 4; s++) {
#pragma unroll
        for (int rr = 0; rr < 2; rr++) {
            int m = wm + s * 16 + gr + rr * 8;
            float p0 = 0.f, p1 = 0.f, p2 = 0.f, p3 = 0.f;
#pragma unroll
            for (int t = 0; t < 4; t++) {
#pragma unroll
                for (int cc = 0; cc < 2; cc++) {
                    int o = wn + t * 8 + 2 * ct + cc;
                    int r = rr * 2 + cc;
                    float v = acc[s][t][r] * A2s[o] + B2s[o];
                    v = (v > 0.f) ? v : 0.01f * v;
                    p0 += v * W2s[0][o];
                    p1 += v * W2s[1][o];
                    p2 += v * W2s[2][o];
                    p3 += v * W2s[3][o];
                }
            }
            atomicAdd(&ys[0][m], p0);
            atomicAdd(&ys[1][m], p1);
            atomicAdd(&ys[2][m], p2);
            atomicAdd(&ys[3][m], p3);
        }
    }
    __syncthreads();
    // channels 1..3 pre-scaled by dis[n] for the weightless scalar Horner
#pragma unroll
    for (int l = 0; l < 2; l++) {
        int li = tid + l * 256;
        int ch = li >> 7, m = li & 127;
        int n = bm + m;
        if (n < NN) {
            float sc = (ch == 0) ? 1.f : g_dis[n];
            g_y[ch][n] = ys[ch][m] * sc;
        }
    }
}

// weightless scalar gather: dst[n] = addin[n] (+bias) + scale(n)*sum src[r]
// sq=1: scale=dis^2 (stay in scaled domain); sq=0: scale=dis (final output)
__global__ void k_shop(float* __restrict__ dst, const float* __restrict__ addin,
                       const float* __restrict__ src, const float* __restrict__ bias,
                       int sq) {
    int n = blockIdx.x * blockDim.x + threadIdx.x;
    if (n >= NN) return;
    float acc = 0.f;
    int e2 = g_off[n + 1];
#pragma unroll 4
    for (int i = g_off[n]; i < e2; i++)
        acc += src[__ldg(&g_csci[i])];
    float dis = g_dis[n];
    float sc = sq ? dis * dis : dis;
    dst[n] = addin[n] + (bias ? bias[0] : 0.f) + sc * acc;
}

// ---------------- launch -----------------------------------------------------
extern "C" void kernel_launch(void* const* d_in, const int* in_sizes, int n_in,
                              void* d_out, int out_size) {
    const float* x     = (const float*)d_in[0];
    const int*   ei    = (const int*)  d_in[1];
    const float* g1    = (const float*)d_in[2];
    const float* b1    = (const float*)d_in[3];
    const float* m1    = (const float*)d_in[4];
    const float* v1    = (const float*)d_in[5];
    const float* W1    = (const float*)d_in[6];
    const float* bias1 = (const float*)d_in[7];
    const float* g2    = (const float*)d_in[8];
    const float* b2    = (const float*)d_in[9];
    const float* m2    = (const float*)d_in[10];
    const float* v2    = (const float*)d_in[11];
    const float* W2    = (const float*)d_in[12];
    const float* bias2 = (const float*)d_in[13];
    float* out = (float*)d_out;

    const int* row = ei;
    const int* col = ei + EE;

    const int T = 256;

    // init (zero deg + all parameter prep) then CSC build
    k_init<<<(NN + T - 1) / T, T>>>(g1, b1, m1, v1, W1, bias1, g2, b2, m2, v2);
    k_deg<<<(EE + T - 1) / T, T>>>(col);
    k_scanA<<<NBLK, SCAN_B>>>();
    k_scanC<<<NBLK, SCAN_B>>>();
    k_fillbn1<<<FB + BB, T>>>(row, col, x);

    // layer-1 propagation: 3 weightless gather hops (scaled domain)
    {
        __half* h0; __half* u0;
        cudaGetSymbolAddress((void**)&h0, g_hbufH);
        cudaGetSymbolAddress((void**)&u0, g_ubufH);
        __half* h1 = h0 + (size_t)NN * DPAD;
        __half* h2 = h1 + (size_t)NN * DPAD;
        __half* h3 = h2 + (size_t)NN * DPAD;
        __half* u1 = u0 + (size_t)NN * DPAD;
        __half* u2 = u1 + (size_t)NN * DPAD;
        int blocks = (NN * NG + T - 1) / T;
        k_hop<<<blocks, T>>>(u0, h1, u1, 1);
        k_hop<<<blocks, T>>>(u1, h2, u2, 1);
        k_hop<<<blocks, T>>>(u2, h3, u2, 0);   // u3 not needed
    }

    // fused fp16 GEMM + BN2 + leaky + W2 projection (g_y, ch1..3 dis-scaled)
    k_gemm<<<(NN + 127) / 128, 256>>>(W2);

    // weightless Horner: out = y0 + A(y1 + A(y2 + A y3)) + bias2
    {
        float* ta; float* tb; float* y0;
        cudaGetSymbolAddress((void**)&ta, g_ta);
        cudaGetSymbolAddress((void**)&tb, g_tb);
        cudaGetSymbolAddress((void**)&y0, g_y);
        float* y1 = y0 + NN; float* y2 = y1 + NN; float* y3 = y2 + NN;
        int bn = (NN + T - 1) / T;
        k_shop<<<bn, T>>>(tb, y2, y3, nullptr, 1);   // t1^ = y2^ + dis^2*sum y3^
        k_shop<<<bn, T>>>(ta, y1, tb, nullptr, 1);   // t2^ = y1^ + dis^2*sum t1^
        k_shop<<<bn, T>>>(out, y0, ta, bias2, 0);    // out = y0 + dis*sum t2^ + b
    }
    (void)in_sizes; (void)n_in; (void)out_size;
}